// round 13
// baseline (speedup 1.0000x reference)
#include <cuda_runtime.h>
#include <cuda_fp16.h>
#include <math.h>
#include <stdint.h>

// Problem constants
#define Bn   2
#define Sn   2048
#define Dn   1024
#define Hn   16
#define DHn  64
#define Mn   (Bn*Sn)          // 4096 rows
#define DFF  (4*Dn)           // 4096
#define DG   (2*Dn)           // 2048
#define EPSV 1e-5f

// -------------------- scratch (device globals; no allocation) --------------------
__device__ __half g_xn1 [Mn*Dn];
__device__ __half g_q   [Mn*Dn];
__device__ __half g_k   [Mn*Dn];
__device__ __half g_v   [Mn*Dn];
__device__ __half g_attn[Mn*Dn];
__device__ float  g_x1  [Mn*Dn];
__device__ __half g_xn2 [Mn*Dn];
__device__ __half g_glu [Mn*DG];
__device__ __half g_wh  [10485760];  // fp16 TRANSPOSED weights [N][K] (W1 col-interleaved)

#define WOFF_Q  0
#define WOFF_K  1048576
#define WOFF_V  2097152
#define WOFF_O  3145728
#define WOFF_1  4194304
#define WOFF_2  8388608

// -------------------- helpers --------------------
__device__ __forceinline__ void mma_f16(float c[4], const uint32_t a[4],
                                        uint32_t b0, uint32_t b1) {
    asm volatile(
        "mma.sync.aligned.m16n8k16.row.col.f32.f16.f16.f32 "
        "{%0,%1,%2,%3}, {%4,%5,%6,%7}, {%8,%9}, {%0,%1,%2,%3};"
        : "+f"(c[0]), "+f"(c[1]), "+f"(c[2]), "+f"(c[3])
        : "r"(a[0]), "r"(a[1]), "r"(a[2]), "r"(a[3]), "r"(b0), "r"(b1));
}

__device__ __forceinline__ uint32_t smem_u32(const void* p) {
    uint32_t a;
    asm("{ .reg .u64 t; cvta.to.shared.u64 t, %1; cvt.u32.u64 %0, t; }"
        : "=r"(a) : "l"(p));
    return a;
}

__device__ __forceinline__ void ldsm4(uint32_t r[4], uint32_t addr) {
    asm volatile("ldmatrix.sync.aligned.m8n8.x4.shared.b16 {%0,%1,%2,%3}, [%4];"
        : "=r"(r[0]), "=r"(r[1]), "=r"(r[2]), "=r"(r[3]) : "r"(addr));
}
__device__ __forceinline__ void ldsm4t(uint32_t r[4], uint32_t addr) {
    asm volatile("ldmatrix.sync.aligned.m8n8.x4.trans.shared.b16 {%0,%1,%2,%3}, [%4];"
        : "=r"(r[0]), "=r"(r[1]), "=r"(r[2]), "=r"(r[3]) : "r"(addr));
}

__device__ __forceinline__ void cp16(uint32_t dst, const void* src) {
    asm volatile("cp.async.cg.shared.global [%0], [%1], 16;" :: "r"(dst), "l"(src) : "memory");
}
__device__ __forceinline__ void cp_commit() { asm volatile("cp.async.commit_group;" ::: "memory"); }
template<int N>
__device__ __forceinline__ void cp_wait() { asm volatile("cp.async.wait_group %0;" :: "n"(N) : "memory"); }

__device__ __forceinline__ uint32_t pack2(float x, float y) {
    __half2 h = __floats2half2_rn(x, y);
    return *(uint32_t*)&h;
}

// ==================== fused weight cvt fp16 + transpose (ONE launch) ====================
// W1 destination rows are column-interleaved: src col j -> dst row 2j (j<2048) / 2(j-2048)+1
__global__ __launch_bounds__(256) void cvtw_all(
    const float* __restrict__ Wq, const float* __restrict__ Wk,
    const float* __restrict__ Wv, const float* __restrict__ Wo,
    const float* __restrict__ W1, const float* __restrict__ W2,
    __half* __restrict__ wh)
{
    __shared__ float tile[32][33];
    const int bid = blockIdx.x;
    const float* src; __half* dst; int K, N, t_;
    bool perm = false;
    if (bid < 4096) {
        const int m = bid >> 10; t_ = bid & 1023;
        src = (m == 0) ? Wq : (m == 1) ? Wk : (m == 2) ? Wv : Wo;
        dst = wh + (size_t)m * 1048576;
        K = 1024; N = 1024;
    } else if (bid < 8192) {
        t_ = bid - 4096; src = W1; dst = wh + WOFF_1; K = 1024; N = 4096; perm = true;
    } else {
        t_ = bid - 8192; src = W2; dst = wh + WOFF_2; K = 2048; N = 1024;
    }
    const int ntx = N >> 5;
    const int bn = (t_ % ntx) * 32, bk = (t_ / ntx) * 32;
    const int tx = threadIdx.x & 31, ty = threadIdx.x >> 5;
    #pragma unroll
    for (int r = 0; r < 4; ++r)
        tile[ty + 8*r][tx] = src[(size_t)(bk + ty + 8*r) * N + bn + tx];
    __syncthreads();
    #pragma unroll
    for (int r = 0; r < 4; ++r) {
        int n = bn + ty + 8*r;
        if (perm) n = (n < 2048) ? 2*n : 2*(n - 2048) + 1;
        dst[(size_t)n * K + bk + tx] = __float2half_rn(tile[tx][ty + 8*r]);
    }
}

// ==================== LayerNorm (fp32 in -> fp16 out) ====================
__global__ __launch_bounds__(256) void ln_kernel(const float* __restrict__ x,
                                                 const float* __restrict__ gamma,
                                                 const float* __restrict__ beta,
                                                 __half* __restrict__ out) {
    const int row = blockIdx.x;
    const int tid = threadIdx.x;
    const float4* xr = (const float4*)(x + (size_t)row * Dn);
    float4 v = xr[tid];
    float s  = v.x + v.y + v.z + v.w;
    float ss = v.x*v.x + v.y*v.y + v.z*v.z + v.w*v.w;
    #pragma unroll
    for (int off = 16; off > 0; off >>= 1) {
        s  += __shfl_xor_sync(0xffffffffu, s,  off);
        ss += __shfl_xor_sync(0xffffffffu, ss, off);
    }
    __shared__ float red[2][8];
    const int wid = tid >> 5, lid = tid & 31;
    if (lid == 0) { red[0][wid] = s; red[1][wid] = ss; }
    __syncthreads();
    __shared__ float smu, srstd;
    if (tid == 0) {
        float ts = 0.f, tss = 0.f;
        #pragma unroll
        for (int i = 0; i < 8; ++i) { ts += red[0][i]; tss += red[1][i]; }
        float mu  = ts * (1.0f / Dn);
        float var = tss * (1.0f / Dn) - mu * mu;
        smu = mu; srstd = rsqrtf(var + EPSV);
    }
    __syncthreads();
    const float mu = smu, rstd = srstd;
    float4 g = ((const float4*)gamma)[tid];
    float4 b = ((const float4*)beta)[tid];
    uint2 u;
    u.x = pack2(g.x * (v.x - mu) * rstd + b.x, g.y * (v.y - mu) * rstd + b.y);
    u.y = pack2(g.z * (v.z - mu) * rstd + b.z, g.w * (v.w - mu) * rstd + b.w);
    ((uint2*)(out + (size_t)row * Dn))[tid] = u;
}

// ==================== FP16 tensor GEMM, cp.async 3-stage, BK=64 ====================
#define BM 128
#define BN 128
#define BKH 64                   // k halves per tile (4 k16 steps)
#define STAGES 3
#define TSH 72                   // stride halves (144B; bank 4r%32 distinct -> ldsm clean)
#define TILE_BYTES (128*TSH*2)   // 18432
#define GT_SMEM (STAGES*2*TILE_BYTES)   // 110592

// MODE: 0 = fp32 out (+RESID), 1 = fp16 out (scaled), 2 = GLU epilogue (fp16 out, N/2 cols)
template<int MODE, bool RESID>
__device__ __forceinline__ void gemm_body(
    const __half* __restrict__ A, const __half* __restrict__ Bt,
    const float* __restrict__ R, void* __restrict__ Cv,
    int M_, int N_, int K_, float oscale)
{
    extern __shared__ char smem[];
    const uint32_t sbase = smem_u32(smem);

    const int tid = threadIdx.x;
    const int bx = blockIdx.x, by = blockIdx.y;
    const int wid = tid >> 5, lane = tid & 31;
    const int wm = (wid >> 2) * 64, wn = (wid & 3) * 32;

    // cp.async: per tile 128 rows x 8 chunks(16B) = 1024; thread: 2 rows x 2 chunks
    const int ld_row = tid >> 2;
    const int ld_ch  = (tid & 3) * 2;

    const int lrow = lane & 15;
    const int lkh  = (lane >> 4) * 8;

    const int nt = K_ >> 6;       // K tiles of 64 halves
    int kload = 0;

    auto issue = [&](int kt, int st) {
        const uint32_t da = sbase + st*(2*TILE_BYTES);
        const uint32_t db = da + TILE_BYTES;
        #pragma unroll
        for (int hrow = 0; hrow < 2; ++hrow) {
            const int r = ld_row + hrow*64;
            #pragma unroll
            for (int c = 0; c < 2; ++c) {
                const int ch = ld_ch + c;
                cp16(da + r*(TSH*2) + ch*16, &A[(size_t)(by*BM + r)*K_ + kt*BKH + ch*8]);
                cp16(db + r*(TSH*2) + ch*16, &Bt[(size_t)(bx*BN + r)*K_ + kt*BKH + ch*8]);
            }
        }
    };

    float acc[4][4][4];
    #pragma unroll
    for (int i = 0; i < 4; ++i)
        #pragma unroll
        for (int j = 0; j < 4; ++j)
            #pragma unroll
            for (int e = 0; e < 4; ++e) acc[i][j][e] = 0.f;

    issue(0, 0); cp_commit();
    if (nt > 1) issue(1, 1);
    cp_commit();
    kload = 2;

    int st = 0;
    for (int kt = 0; kt < nt; ++kt) {
        cp_wait<STAGES-2>();
        __syncthreads();
        const uint32_t sa = sbase + st*(2*TILE_BYTES);
        const uint32_t sb = sa + TILE_BYTES;
        #pragma unroll
        for (int kk = 0; kk < 4; ++kk) {        // four k16 steps
            uint32_t afr[4][4], bq[2][4];
            #pragma unroll
            for (int i = 0; i < 4; ++i)
                ldsm4(afr[i], sa + ((wm + i*16 + lrow)*TSH + kk*16 + lkh)*2);
            #pragma unroll
            for (int jj = 0; jj < 2; ++jj)
                ldsm4(bq[jj], sb + ((wn + jj*16 + lrow)*TSH + kk*16 + lkh)*2);
            #pragma unroll
            for (int i = 0; i < 4; ++i) {
                #pragma unroll
                for (int jj = 0; jj < 2; ++jj) {
                    mma_f16(acc[i][jj*2  ], afr[i], bq[jj][0], bq[jj][2]);
                    mma_f16(acc[i][jj*2+1], afr[i], bq[jj][1], bq[jj][3]);
                }
            }
        }
        if (kload < nt) {
            issue(kload, (st + 2 >= STAGES) ? st + 2 - STAGES : st + 2);
            ++kload;
        }
        cp_commit();
        if (++st == STAGES) st = 0;
    }

    // epilogue
    const int eg = lane >> 2, et = lane & 3;
    #pragma unroll
    for (int i = 0; i < 4; ++i) {
        const int row0 = by*BM + wm + i*16 + eg;
        const int row1 = row0 + 8;
        #pragma unroll
        for (int j = 0; j < 4; ++j) {
            const int col = bx*BN + wn + j*8 + et*2;
            if (MODE == 2) {
                // GLU: even col = left, odd col = right (interleaved W1)
                __half* C = (__half*)Cv;
                const int colh = col >> 1;
                const int No = N_ >> 1;
                float g0 = acc[i][j][0] / (1.f + __expf(-acc[i][j][1]));
                float g1 = acc[i][j][2] / (1.f + __expf(-acc[i][j][3]));
                C[(size_t)row0*No + colh] = __float2half_rn(g0);
                C[(size_t)row1*No + colh] = __float2half_rn(g1);
            } else if (MODE == 1) {
                __half* C = (__half*)Cv;
                *(uint32_t*)&C[(size_t)row0*N_ + col] =
                    pack2(acc[i][j][0]*oscale, acc[i][j][1]*oscale);
                *(uint32_t*)&C[(size_t)row1*N_ + col] =
                    pack2(acc[i][j][2]*oscale, acc[i][j][3]*oscale);
            } else {
                float* C = (float*)Cv;
                float2 v0 = { acc[i][j][0], acc[i][j][1] };
                float2 v1 = { acc[i][j][2], acc[i][j][3] };
                if (RESID) {
                    float2 r0 = *(const float2*)&R[(size_t)row0*N_ + col];
                    float2 r1 = *(const float2*)&R[(size_t)row1*N_ + col];
                    v0.x += r0.x; v0.y += r0.y;
                    v1.x += r1.x; v1.y += r1.y;
                }
                *(float2*)&C[(size_t)row0*N_ + col] = v0;
                *(float2*)&C[(size_t)row1*N_ + col] = v1;
            }
        }
    }
}

template<int MODE, bool RESID>
__global__ __launch_bounds__(256, 2) void gemm_k(
    const __half* __restrict__ A, const __half* __restrict__ Bt,
    const float* __restrict__ R, void* __restrict__ Cv,
    int M_, int N_, int K_)
{
    gemm_body<MODE, RESID>(A, Bt, R, Cv, M_, N_, K_, 1.0f);
}

// fused QKV; q output pre-scaled by (1/sqrt(DH)) * log2(e) for exp2-based softmax
#define QSCALE (0.125f * 1.4426950408889634f)
__global__ __launch_bounds__(256, 2) void gemm_qkv(
    const __half* __restrict__ A, const __half* __restrict__ W,
    __half* __restrict__ q, __half* __restrict__ k, __half* __restrict__ v)
{
    const int z = blockIdx.z;
    const __half* Bt = W + (z == 0 ? WOFF_Q : z == 1 ? WOFF_K : WOFF_V);
    __half* C = (z == 0) ? q : (z == 1) ? k : v;
    gemm_body<1, false>(A, Bt, nullptr, C, Mn, Dn, Dn, z == 0 ? QSCALE : 1.0f);
}

// ==================== causal flash attention: balanced qt-pairing, exp2 softmax ====================
// grid (16, H, B), 128 threads (4 warps x 16 q rows). Block p handles qt=31-p then qt=p.
#define KVS 72
#define KV_STAGE_BYTES (2*64*KVS*2)
#define ATTN_SMEM (2*KV_STAGE_BYTES)      // 36864
#define NQT (Sn/64)                       // 32

__global__ __launch_bounds__(128, 3) void attn_f16(
    const __half* __restrict__ Q, const __half* __restrict__ K,
    const __half* __restrict__ V, const int* __restrict__ mask,
    __half* __restrict__ O) {
    extern __shared__ __half smh[];
    const uint32_t sm0 = smem_u32(smh);
    __shared__ uint32_t mbits[2][2];

    const int pair = blockIdx.x;          // 0..15
    const int h = blockIdx.y, b = blockIdx.z;
    const int tid = threadIdx.x;
    const int wid = tid >> 5, lane = tid & 31;
    const int g = lane >> 2, t = lane & 3;
    const int lrow = lane & 15;
    const int lkh  = (lane >> 4) * 8;

    #pragma unroll
    for (int ph = 0; ph < 2; ++ph) {
        const int qt = (ph == 0) ? (NQT - 1 - pair) : pair;   // heavy first

        // Q fragments (pre-scaled by 0.125*log2e)
        const __half* Qb = Q + ((size_t)(b*Sn + qt*64 + wid*16))*Dn + h*DHn;
        uint32_t qa[4][4];
        #pragma unroll
        for (int ks = 0; ks < 4; ++ks) {
            qa[ks][0] = *(const uint32_t*)&Qb[(size_t)(g    )*Dn + ks*16 + 2*t];
            qa[ks][1] = *(const uint32_t*)&Qb[(size_t)(g + 8)*Dn + ks*16 + 2*t];
            qa[ks][2] = *(const uint32_t*)&Qb[(size_t)(g    )*Dn + ks*16 + 8 + 2*t];
            qa[ks][3] = *(const uint32_t*)&Qb[(size_t)(g + 8)*Dn + ks*16 + 8 + 2*t];
        }

        auto load_kv = [&](int kt, int st) {
            const uint32_t ks_u = sm0 + st*KV_STAGE_BYTES;
            const uint32_t vs_u = ks_u + 64*KVS*2;
            const __half* Kb = K + (size_t)(b*Sn + kt*64)*Dn + h*DHn;
            const __half* Vb = V + (size_t)(b*Sn + kt*64)*Dn + h*DHn;
            #pragma unroll
            for (int c = 0; c < 4; ++c) {
                const int idx = tid + c*128;
                const int rr = idx >> 3, ch = idx & 7;
                cp16(ks_u + rr*(KVS*2) + ch*16, Kb + (size_t)rr*Dn + ch*8);
                cp16(vs_u + rr*(KVS*2) + ch*16, Vb + (size_t)rr*Dn + ch*8);
            }
            if (tid < 64) {
                const int val = mask[b*Sn + kt*64 + tid];
                const unsigned bal = __ballot_sync(0xffffffffu, val != 0);
                if ((tid & 31) == 0) mbits[st][tid >> 5] = bal;
            }
        };

        float o[8][4];
        #pragma unroll
        for (int j = 0; j < 8; ++j)
            #pragma unroll
            for (int e = 0; e < 4; ++e) o[j][e] = 0.f;
        float m0 = -1e30f, m1 = -1e30f, l0 = 0.f, l1 = 0.f;

        const int rowg0 = qt*64 + wid*16 + g;
        const int rowg1 = rowg0 + 8;

        load_kv(0, 0); cp_commit();
        if (qt >= 1) load_kv(1, 1);
        cp_commit();

        int buf = 0;
        for (int kt = 0; kt <= qt; ++kt) {
            cp_wait<1>();
            __syncthreads();
            const uint32_t ks_u = sm0 + buf*KV_STAGE_BYTES;
            const uint32_t vs_u = ks_u + 64*KVS*2;

            // S' = log2e * Q @ K^T / 8 (scale folded into Q)
            float sc[8][4];
            #pragma unroll
            for (int j = 0; j < 8; ++j)
                #pragma unroll
                for (int e = 0; e < 4; ++e) sc[j][e] = 0.f;
            #pragma unroll
            for (int ks = 0; ks < 4; ++ks) {
                #pragma unroll
                for (int jj = 0; jj < 4; ++jj) {
                    uint32_t bq[4];
                    ldsm4(bq, ks_u + ((jj*16 + lrow)*KVS + ks*16 + lkh)*2);
                    mma_f16(sc[jj*2  ], qa[ks], bq[0], bq[2]);
                    mma_f16(sc[jj*2+1], qa[ks], bq[1], bq[3]);
                }
            }

            const uint32_t mb0 = mbits[buf][0], mb1 = mbits[buf][1];
            const bool need_mask = (kt == qt) || ((mb0 & mb1) != 0xffffffffu);
            if (need_mask) {
                #pragma unroll
                for (int j = 0; j < 8; ++j) {
                    #pragma unroll
                    for (int e = 0; e < 4; ++e) {
                        const int cl  = j*8 + t*2 + (e & 1);
                        const int kg  = kt*64 + cl;
                        const int row = (e < 2) ? rowg0 : rowg1;
                        const bool km = (cl < 32) ? ((mb0 >> cl) & 1u)
                                                  : ((mb1 >> (cl - 32)) & 1u);
                        const bool ok = (kg <= row) && km;
                        sc[j][e] = ok ? sc[j][e] : -1e30f;
                    }
                }
            }

            // online softmax in base-2 domain (exp2f = single MUFU)
            float rm0 = -1e30f, rm1 = -1e30f;
            #pragma unroll
            for (int j = 0; j < 8; ++j) {
                rm0 = fmaxf(rm0, fmaxf(sc[j][0], sc[j][1]));
                rm1 = fmaxf(rm1, fmaxf(sc[j][2], sc[j][3]));
            }
            rm0 = fmaxf(rm0, __shfl_xor_sync(0xffffffffu, rm0, 1));
            rm0 = fmaxf(rm0, __shfl_xor_sync(0xffffffffu, rm0, 2));
            rm1 = fmaxf(rm1, __shfl_xor_sync(0xffffffffu, rm1, 1));
            rm1 = fmaxf(rm1, __shfl_xor_sync(0xffffffffu, rm1, 2));
            const float mn0 = fmaxf(m0, rm0), mn1 = fmaxf(m1, rm1);
            const float al0 = exp2f(m0 - mn0), al1 = exp2f(m1 - mn1);
            float s0 = 0.f, s1 = 0.f;
            #pragma unroll
            for (int j = 0; j < 8; ++j) {
                sc[j][0] = exp2f(sc[j][0] - mn0);
                sc[j][1] = exp2f(sc[j][1] - mn0);
                sc[j][2] = exp2f(sc[j][2] - mn1);
                sc[j][3] = exp2f(sc[j][3] - mn1);
                s0 += sc[j][0] + sc[j][1];
                s1 += sc[j][2] + sc[j][3];
            }
            s0 += __shfl_xor_sync(0xffffffffu, s0, 1);
            s0 += __shfl_xor_sync(0xffffffffu, s0, 2);
            s1 += __shfl_xor_sync(0xffffffffu, s1, 1);
            s1 += __shfl_xor_sync(0xffffffffu, s1, 2);
            l0 = l0 * al0 + s0;  m0 = mn0;
            l1 = l1 * al1 + s1;  m1 = mn1;
            #pragma unroll
            for (int j = 0; j < 8; ++j) {
                o[j][0] *= al0; o[j][1] *= al0;
                o[j][2] *= al1; o[j][3] *= al1;
            }

            // O += P @ V (P fragments are direct repacks of sc)
            #pragma unroll
            for (int ks = 0; ks < 4; ++ks) {
                uint32_t pa[4];
                pa[0] = pack2(sc[2*ks  ][0], sc[2*ks  ][1]);
                pa[1] = pack2(sc[2*ks  ][2], sc[2*ks  ][3]);
                pa[2] = pack2(sc[2*ks+1][0], sc[2*ks+1][1]);
                pa[3] = pack2(sc[2*ks+1][2], sc[2*ks+1][3]);
                #pragma unroll
                for (int jj = 0; jj < 4; ++jj) {
                    uint32_t bq[4];
                    ldsm4t(bq, vs_u + ((ks*16 + lrow)*KVS + jj*16 + lkh)*2);
                    mma_f16(o[jj*2  ], pa, bq[0], bq[1]);
                    mma_f16(o[jj*2+1], pa, bq[2], bq[3]);
                }
            }

            __syncthreads();
            if (kt + 2 <= qt) load_kv(kt + 2, buf);
            cp_commit();
            buf ^= 1;
        }

        const float i0 = 1.f / l0, i1 = 1.f / l1;
        __half* Ob = O + ((size_t)(b*Sn + qt*64 + wid*16))*Dn + h*DHn;
        #pragma unroll
        for (int j = 0; j < 8; ++j) {
            *(uint32_t*)&Ob[(size_t)(g    )*Dn + j*8 + t*2] = pack2(o[j][0]*i0, o[j][1]*i0);
            *(uint32_t*)&Ob[(size_t)(g + 8)*Dn + j*8 + t*2] = pack2(o[j][2]*i1, o[j][3]*i1);
        }
        __syncthreads();   // buffers reused next phase
    }
}

// ==================== launch ====================
extern "C" void kernel_launch(void* const* d_in, const int* in_sizes, int n_in,
                              void* d_out, int out_size) {
    const float* x     = (const float*)d_in[0];
    const int*   amask = (const int*)  d_in[1];
    const float* Wq    = (const float*)d_in[2];
    const float* Wk    = (const float*)d_in[3];
    const float* Wv    = (const float*)d_in[4];
    const float* Wo    = (const float*)d_in[5];
    const float* W1    = (const float*)d_in[6];
    const float* W2    = (const float*)d_in[7];
    const float* gamma1= (const float*)d_in[8];
    const float* beta1 = (const float*)d_in[9];
    const float* gamma2= (const float*)d_in[10];
    const float* beta2 = (const float*)d_in[11];
    float* out = (float*)d_out;

    __half *xn1, *q, *k, *v, *attn, *xn2, *glu, *wh;
    float *x1;
    cudaGetSymbolAddress((void**)&xn1,  g_xn1);
    cudaGetSymbolAddress((void**)&q,    g_q);
    cudaGetSymbolAddress((void**)&k,    g_k);
    cudaGetSymbolAddress((void**)&v,    g_v);
    cudaGetSymbolAddress((void**)&attn, g_attn);
    cudaGetSymbolAddress((void**)&x1,   g_x1);
    cudaGetSymbolAddress((void**)&xn2,  g_xn2);
    cudaGetSymbolAddress((void**)&glu,  g_glu);
    cudaGetSymbolAddress((void**)&wh,   g_wh);

    cudaFuncSetAttribute(attn_f16, cudaFuncAttributeMaxDynamicSharedMemorySize, ATTN_SMEM);
    cudaFuncSetAttribute(gemm_qkv, cudaFuncAttributeMaxDynamicSharedMemorySize, GT_SMEM);
    cudaFuncSetAttribute((const void*)gemm_k<0,true>,  cudaFuncAttributeMaxDynamicSharedMemorySize, GT_SMEM);
    cudaFuncSetAttribute((const void*)gemm_k<2,false>, cudaFuncAttributeMaxDynamicSharedMemorySize, GT_SMEM);

    // 0. fused weight convert+transpose (W1 col-interleaved)
    cvtw_all<<<10240, 256>>>(Wq, Wk, Wv, Wo, W1, W2, wh);

    // 1. LN1 -> fp16
    ln_kernel<<<Mn, 256>>>(x, gamma1, beta1, xn1);

    // 2. fused Q,K,V projections -> fp16 (q pre-scaled for exp2 softmax)
    dim3 gQKV(Dn/BN, Mn/BM, 3);
    gemm_qkv<<<gQKV, 256, GT_SMEM>>>(xn1, wh, q, k, v);

    // 3. causal attention -> fp16 (balanced qt pairs, 512 blocks)
    dim3 gA(NQT/2, Hn, Bn);
    attn_f16<<<gA, 128, ATTN_SMEM>>>(q, k, v, amask, attn);

    // 4. output projection + residual -> fp32 x1
    dim3 gD(Dn/BN, Mn/BM);
    gemm_k<0,true><<<gD, 256, GT_SMEM>>>(attn, wh + WOFF_O, x, x1, Mn, Dn, Dn);

    // 5. LN2 -> fp16
    ln_kernel<<<Mn, 256>>>(x1, gamma2, beta2, xn2);

    // 6. W1 + GLU fused -> fp16 glu [Mn, 2048]
    dim3 gF(DFF/BN, Mn/BM);
    gemm_k<2,false><<<gF, 256, GT_SMEM>>>(xn2, wh + WOFF_1, nullptr, glu, Mn, DFF, Dn);

    // 7. W2 + residual -> fp32 out
    gemm_k<0,true><<<gD, 256, GT_SMEM>>>(glu, wh + WOFF_2, x1, out, Mn, Dn, DG);
}

// round 14
// speedup vs baseline: 1.0108x; 1.0108x over previous
#include <cuda_runtime.h>
#include <cuda_fp16.h>
#include <math.h>
#include <stdint.h>

// Problem constants
#define Bn   2
#define Sn   2048
#define Dn   1024
#define Hn   16
#define DHn  64
#define Mn   (Bn*Sn)          // 4096 rows
#define DFF  (4*Dn)           // 4096
#define DG   (2*Dn)           // 2048
#define EPSV 1e-5f

// -------------------- scratch (device globals; no allocation) --------------------
__device__ __half g_xn1 [Mn*Dn];
__device__ __half g_q   [Mn*Dn];
__device__ __half g_k   [Mn*Dn];
__device__ __half g_v   [Mn*Dn];
__device__ __half g_attn[Mn*Dn];
__device__ float  g_x1  [Mn*Dn];
__device__ __half g_xn2 [Mn*Dn];
__device__ __half g_glu [Mn*DG];
__device__ __half g_wh  [10485760];  // fp16 TRANSPOSED weights [N][K] (W1 col-interleaved)

#define WOFF_Q  0
#define WOFF_K  1048576
#define WOFF_V  2097152
#define WOFF_O  3145728
#define WOFF_1  4194304
#define WOFF_2  8388608

// -------------------- helpers --------------------
__device__ __forceinline__ void mma_f16(float c[4], const uint32_t a[4],
                                        uint32_t b0, uint32_t b1) {
    asm volatile(
        "mma.sync.aligned.m16n8k16.row.col.f32.f16.f16.f32 "
        "{%0,%1,%2,%3}, {%4,%5,%6,%7}, {%8,%9}, {%0,%1,%2,%3};"
        : "+f"(c[0]), "+f"(c[1]), "+f"(c[2]), "+f"(c[3])
        : "r"(a[0]), "r"(a[1]), "r"(a[2]), "r"(a[3]), "r"(b0), "r"(b1));
}

__device__ __forceinline__ uint32_t smem_u32(const void* p) {
    uint32_t a;
    asm("{ .reg .u64 t; cvta.to.shared.u64 t, %1; cvt.u32.u64 %0, t; }"
        : "=r"(a) : "l"(p));
    return a;
}

__device__ __forceinline__ void ldsm4(uint32_t r[4], uint32_t addr) {
    asm volatile("ldmatrix.sync.aligned.m8n8.x4.shared.b16 {%0,%1,%2,%3}, [%4];"
        : "=r"(r[0]), "=r"(r[1]), "=r"(r[2]), "=r"(r[3]) : "r"(addr));
}
__device__ __forceinline__ void ldsm4t(uint32_t r[4], uint32_t addr) {
    asm volatile("ldmatrix.sync.aligned.m8n8.x4.trans.shared.b16 {%0,%1,%2,%3}, [%4];"
        : "=r"(r[0]), "=r"(r[1]), "=r"(r[2]), "=r"(r[3]) : "r"(addr));
}

__device__ __forceinline__ void cp16(uint32_t dst, const void* src) {
    asm volatile("cp.async.cg.shared.global [%0], [%1], 16;" :: "r"(dst), "l"(src) : "memory");
}
__device__ __forceinline__ void cp_commit() { asm volatile("cp.async.commit_group;" ::: "memory"); }
template<int N>
__device__ __forceinline__ void cp_wait() { asm volatile("cp.async.wait_group %0;" :: "n"(N) : "memory"); }

__device__ __forceinline__ uint32_t pack2(float x, float y) {
    __half2 h = __floats2half2_rn(x, y);
    return *(uint32_t*)&h;
}

// ==================== fused weight cvt fp16 + transpose (ONE launch) ====================
// W1 destination rows are column-interleaved: src col j -> dst row 2j (j<2048) / 2(j-2048)+1
__global__ __launch_bounds__(256) void cvtw_all(
    const float* __restrict__ Wq, const float* __restrict__ Wk,
    const float* __restrict__ Wv, const float* __restrict__ Wo,
    const float* __restrict__ W1, const float* __restrict__ W2,
    __half* __restrict__ wh)
{
    __shared__ float tile[32][33];
    const int bid = blockIdx.x;
    const float* src; __half* dst; int K, N, t_;
    bool perm = false;
    if (bid < 4096) {
        const int m = bid >> 10; t_ = bid & 1023;
        src = (m == 0) ? Wq : (m == 1) ? Wk : (m == 2) ? Wv : Wo;
        dst = wh + (size_t)m * 1048576;
        K = 1024; N = 1024;
    } else if (bid < 8192) {
        t_ = bid - 4096; src = W1; dst = wh + WOFF_1; K = 1024; N = 4096; perm = true;
    } else {
        t_ = bid - 8192; src = W2; dst = wh + WOFF_2; K = 2048; N = 1024;
    }
    const int ntx = N >> 5;
    const int bn = (t_ % ntx) * 32, bk = (t_ / ntx) * 32;
    const int tx = threadIdx.x & 31, ty = threadIdx.x >> 5;
    #pragma unroll
    for (int r = 0; r < 4; ++r)
        tile[ty + 8*r][tx] = src[(size_t)(bk + ty + 8*r) * N + bn + tx];
    __syncthreads();
    #pragma unroll
    for (int r = 0; r < 4; ++r) {
        int n = bn + ty + 8*r;
        if (perm) n = (n < 2048) ? 2*n : 2*(n - 2048) + 1;
        dst[(size_t)n * K + bk + tx] = __float2half_rn(tile[tx][ty + 8*r]);
    }
}

// ==================== LayerNorm (fp32 in -> fp16 out) ====================
__global__ __launch_bounds__(256) void ln_kernel(const float* __restrict__ x,
                                                 const float* __restrict__ gamma,
                                                 const float* __restrict__ beta,
                                                 __half* __restrict__ out) {
    const int row = blockIdx.x;
    const int tid = threadIdx.x;
    const float4* xr = (const float4*)(x + (size_t)row * Dn);
    float4 v = xr[tid];
    float s  = v.x + v.y + v.z + v.w;
    float ss = v.x*v.x + v.y*v.y + v.z*v.z + v.w*v.w;
    #pragma unroll
    for (int off = 16; off > 0; off >>= 1) {
        s  += __shfl_xor_sync(0xffffffffu, s,  off);
        ss += __shfl_xor_sync(0xffffffffu, ss, off);
    }
    __shared__ float red[2][8];
    const int wid = tid >> 5, lid = tid & 31;
    if (lid == 0) { red[0][wid] = s; red[1][wid] = ss; }
    __syncthreads();
    __shared__ float smu, srstd;
    if (tid == 0) {
        float ts = 0.f, tss = 0.f;
        #pragma unroll
        for (int i = 0; i < 8; ++i) { ts += red[0][i]; tss += red[1][i]; }
        float mu  = ts * (1.0f / Dn);
        float var = tss * (1.0f / Dn) - mu * mu;
        smu = mu; srstd = rsqrtf(var + EPSV);
    }
    __syncthreads();
    const float mu = smu, rstd = srstd;
    float4 g = ((const float4*)gamma)[tid];
    float4 b = ((const float4*)beta)[tid];
    uint2 u;
    u.x = pack2(g.x * (v.x - mu) * rstd + b.x, g.y * (v.y - mu) * rstd + b.y);
    u.y = pack2(g.z * (v.z - mu) * rstd + b.z, g.w * (v.w - mu) * rstd + b.w);
    ((uint2*)(out + (size_t)row * Dn))[tid] = u;
}

// ==================== FP16 tensor GEMM, cp.async 3-stage + ldmatrix (R12 config) ====================
#define BM 128
#define BN 128
#define BKH 32
#define STAGES 3
#define TSH 56
#define TILE_BYTES (128*TSH*2)
#define GT_SMEM (STAGES*2*TILE_BYTES)   // 86016

// MODE: 0 = fp32 out (+RESID), 1 = fp16 out (scaled), 2 = GLU epilogue (fp16 out, N/2 cols)
template<int MODE, bool RESID>
__device__ __forceinline__ void gemm_body(
    const __half* __restrict__ A, const __half* __restrict__ Bt,
    const float* __restrict__ R, void* __restrict__ Cv,
    int M_, int N_, int K_, float oscale)
{
    extern __shared__ char smem[];
    const uint32_t sbase = smem_u32(smem);

    const int tid = threadIdx.x;
    const int bx = blockIdx.x, by = blockIdx.y;
    const int wid = tid >> 5, lane = tid & 31;
    const int wm = (wid >> 2) * 64, wn = (wid & 3) * 32;

    const int ld_row = tid >> 2;
    const int ld_ch  = tid & 3;

    const int lrow = lane & 15;
    const int lkh  = (lane >> 4) * 8;

    const int nt = K_ >> 5;
    int kload = 0;

    auto issue = [&](int kt, int st) {
        const uint32_t da = sbase + st*(2*TILE_BYTES);
        const uint32_t db = da + TILE_BYTES;
        cp16(da + (ld_row     )*(TSH*2) + ld_ch*16,
             &A[(size_t)(by*BM + ld_row     )*K_ + kt*BKH + ld_ch*8]);
        cp16(da + (ld_row + 64)*(TSH*2) + ld_ch*16,
             &A[(size_t)(by*BM + ld_row + 64)*K_ + kt*BKH + ld_ch*8]);
        cp16(db + (ld_row     )*(TSH*2) + ld_ch*16,
             &Bt[(size_t)(bx*BN + ld_row     )*K_ + kt*BKH + ld_ch*8]);
        cp16(db + (ld_row + 64)*(TSH*2) + ld_ch*16,
             &Bt[(size_t)(bx*BN + ld_row + 64)*K_ + kt*BKH + ld_ch*8]);
    };

    float acc[4][4][4];
    #pragma unroll
    for (int i = 0; i < 4; ++i)
        #pragma unroll
        for (int j = 0; j < 4; ++j)
            #pragma unroll
            for (int e = 0; e < 4; ++e) acc[i][j][e] = 0.f;

    issue(0, 0); cp_commit();
    issue(1, 1); cp_commit();
    kload = 2;

    int st = 0;
    for (int kt = 0; kt < nt; ++kt) {
        cp_wait<STAGES-2>();
        __syncthreads();
        const uint32_t sa = sbase + st*(2*TILE_BYTES);
        const uint32_t sb = sa + TILE_BYTES;
        #pragma unroll
        for (int kk = 0; kk < 2; ++kk) {
            uint32_t afr[4][4], bq[2][4];
            #pragma unroll
            for (int i = 0; i < 4; ++i)
                ldsm4(afr[i], sa + ((wm + i*16 + lrow)*TSH + kk*16 + lkh)*2);
            #pragma unroll
            for (int jj = 0; jj < 2; ++jj)
                ldsm4(bq[jj], sb + ((wn + jj*16 + lrow)*TSH + kk*16 + lkh)*2);
            #pragma unroll
            for (int i = 0; i < 4; ++i) {
                #pragma unroll
                for (int jj = 0; jj < 2; ++jj) {
                    mma_f16(acc[i][jj*2  ], afr[i], bq[jj][0], bq[jj][2]);
                    mma_f16(acc[i][jj*2+1], afr[i], bq[jj][1], bq[jj][3]);
                }
            }
        }
        if (kload < nt) {
            issue(kload, (st + 2 >= STAGES) ? st + 2 - STAGES : st + 2);
            ++kload;
        }
        cp_commit();
        if (++st == STAGES) st = 0;
    }

    // epilogue
    const int eg = lane >> 2, et = lane & 3;
    #pragma unroll
    for (int i = 0; i < 4; ++i) {
        const int row0 = by*BM + wm + i*16 + eg;
        const int row1 = row0 + 8;
        #pragma unroll
        for (int j = 0; j < 4; ++j) {
            const int col = bx*BN + wn + j*8 + et*2;
            if (MODE == 2) {
                __half* C = (__half*)Cv;
                const int colh = col >> 1;
                const int No = N_ >> 1;
                float g0 = acc[i][j][0] / (1.f + __expf(-acc[i][j][1]));
                float g1 = acc[i][j][2] / (1.f + __expf(-acc[i][j][3]));
                C[(size_t)row0*No + colh] = __float2half_rn(g0);
                C[(size_t)row1*No + colh] = __float2half_rn(g1);
            } else if (MODE == 1) {
                __half* C = (__half*)Cv;
                *(uint32_t*)&C[(size_t)row0*N_ + col] =
                    pack2(acc[i][j][0]*oscale, acc[i][j][1]*oscale);
                *(uint32_t*)&C[(size_t)row1*N_ + col] =
                    pack2(acc[i][j][2]*oscale, acc[i][j][3]*oscale);
            } else {
                float* C = (float*)Cv;
                float2 v0 = { acc[i][j][0], acc[i][j][1] };
                float2 v1 = { acc[i][j][2], acc[i][j][3] };
                if (RESID) {
                    float2 r0 = *(const float2*)&R[(size_t)row0*N_ + col];
                    float2 r1 = *(const float2*)&R[(size_t)row1*N_ + col];
                    v0.x += r0.x; v0.y += r0.y;
                    v1.x += r1.x; v1.y += r1.y;
                }
                *(float2*)&C[(size_t)row0*N_ + col] = v0;
                *(float2*)&C[(size_t)row1*N_ + col] = v1;
            }
        }
    }
}

template<int MODE, bool RESID>
__global__ __launch_bounds__(256, 2) void gemm_k(
    const __half* __restrict__ A, const __half* __restrict__ Bt,
    const float* __restrict__ R, void* __restrict__ Cv,
    int M_, int N_, int K_)
{
    gemm_body<MODE, RESID>(A, Bt, R, Cv, M_, N_, K_, 1.0f);
}

// fused QKV; q output pre-scaled by (1/sqrt(DH)) * log2(e) for exp2-based softmax
#define QSCALE (0.125f * 1.4426950408889634f)
__global__ __launch_bounds__(256, 2) void gemm_qkv(
    const __half* __restrict__ A, const __half* __restrict__ W,
    __half* __restrict__ q, __half* __restrict__ k, __half* __restrict__ v)
{
    const int z = blockIdx.z;
    const __half* Bt = W + (z == 0 ? WOFF_Q : z == 1 ? WOFF_K : WOFF_V);
    __half* C = (z == 0) ? q : (z == 1) ? k : v;
    gemm_body<1, false>(A, Bt, nullptr, C, Mn, Dn, Dn, z == 0 ? QSCALE : 1.0f);
}

// ==================== causal flash attention: qt-pairing + 3-stage KV ring ====================
// grid (16, H, B), 128 threads. Block p: qt=31-p then qt=p. ONE barrier per kv tile.
#define KVS 72
#define KV_STAGE_BYTES (2*64*KVS*2)       // 18432
#define KV_STAGES 3
#define ATTN_SMEM (KV_STAGES*KV_STAGE_BYTES)   // 55296
#define NQT (Sn/64)                       // 32

__global__ __launch_bounds__(128, 3) void attn_f16(
    const __half* __restrict__ Q, const __half* __restrict__ K,
    const __half* __restrict__ V, const int* __restrict__ mask,
    __half* __restrict__ O) {
    extern __shared__ __half smh[];
    const uint32_t sm0 = smem_u32(smh);
    __shared__ uint32_t mbits[KV_STAGES][2];

    const int pair = blockIdx.x;          // 0..15
    const int h = blockIdx.y, b = blockIdx.z;
    const int tid = threadIdx.x;
    const int wid = tid >> 5, lane = tid & 31;
    const int g = lane >> 2, t = lane & 3;
    const int lrow = lane & 15;
    const int lkh  = (lane >> 4) * 8;

    #pragma unroll
    for (int ph = 0; ph < 2; ++ph) {
        const int qt = (ph == 0) ? (NQT - 1 - pair) : pair;   // heavy first

        // Q fragments (pre-scaled by 0.125*log2e)
        const __half* Qb = Q + ((size_t)(b*Sn + qt*64 + wid*16))*Dn + h*DHn;
        uint32_t qa[4][4];
        #pragma unroll
        for (int ks = 0; ks < 4; ++ks) {
            qa[ks][0] = *(const uint32_t*)&Qb[(size_t)(g    )*Dn + ks*16 + 2*t];
            qa[ks][1] = *(const uint32_t*)&Qb[(size_t)(g + 8)*Dn + ks*16 + 2*t];
            qa[ks][2] = *(const uint32_t*)&Qb[(size_t)(g    )*Dn + ks*16 + 8 + 2*t];
            qa[ks][3] = *(const uint32_t*)&Qb[(size_t)(g + 8)*Dn + ks*16 + 8 + 2*t];
        }

        auto load_kv = [&](int kt, int st) {
            const uint32_t ks_u = sm0 + st*KV_STAGE_BYTES;
            const uint32_t vs_u = ks_u + 64*KVS*2;
            const __half* Kb = K + (size_t)(b*Sn + kt*64)*Dn + h*DHn;
            const __half* Vb = V + (size_t)(b*Sn + kt*64)*Dn + h*DHn;
            #pragma unroll
            for (int c = 0; c < 4; ++c) {
                const int idx = tid + c*128;
                const int rr = idx >> 3, ch = idx & 7;
                cp16(ks_u + rr*(KVS*2) + ch*16, Kb + (size_t)rr*Dn + ch*8);
                cp16(vs_u + rr*(KVS*2) + ch*16, Vb + (size_t)rr*Dn + ch*8);
            }
            if (tid < 64) {
                const int val = mask[b*Sn + kt*64 + tid];
                const unsigned bal = __ballot_sync(0xffffffffu, val != 0);
                if ((tid & 31) == 0) mbits[st][tid >> 5] = bal;
            }
        };

        float o[8][4];
        #pragma unroll
        for (int j = 0; j < 8; ++j)
            #pragma unroll
            for (int e = 0; e < 4; ++e) o[j][e] = 0.f;
        float m0 = -1e30f, m1 = -1e30f, l0 = 0.f, l1 = 0.f;

        const int rowg0 = qt*64 + wid*16 + g;
        const int rowg1 = rowg0 + 8;

        // prologue: groups numbered == kt (empty commits keep numbering)
        load_kv(0, 0); cp_commit();
        if (qt >= 1) load_kv(1, 1);
        cp_commit();

        for (int kt = 0; kt <= qt; ++kt) {
            const int buf = kt % KV_STAGES;
            cp_wait<1>();           // group kt complete; group kt+1 may be in flight
            __syncthreads();        // ONE barrier per tile (3-stage ring makes the
                                    // pre-reload barrier redundant)
            const uint32_t ks_u = sm0 + buf*KV_STAGE_BYTES;
            const uint32_t vs_u = ks_u + 64*KVS*2;
            const uint32_t mb0 = mbits[buf][0], mb1 = mbits[buf][1];

            // S' = log2e * Q @ K^T / 8 (scale folded into Q)
            float sc[8][4];
            #pragma unroll
            for (int j = 0; j < 8; ++j)
                #pragma unroll
                for (int e = 0; e < 4; ++e) sc[j][e] = 0.f;
            #pragma unroll
            for (int ks = 0; ks < 4; ++ks) {
                #pragma unroll
                for (int jj = 0; jj < 4; ++jj) {
                    uint32_t bq[4];
                    ldsm4(bq, ks_u + ((jj*16 + lrow)*KVS + ks*16 + lkh)*2);
                    mma_f16(sc[jj*2  ], qa[ks], bq[0], bq[2]);
                    mma_f16(sc[jj*2+1], qa[ks], bq[1], bq[3]);
                }
            }

            const bool need_mask = (kt == qt) || ((mb0 & mb1) != 0xffffffffu);
            if (need_mask) {
                #pragma unroll
                for (int j = 0; j < 8; ++j) {
                    #pragma unroll
                    for (int e = 0; e < 4; ++e) {
                        const int cl  = j*8 + t*2 + (e & 1);
                        const int kg  = kt*64 + cl;
                        const int row = (e < 2) ? rowg0 : rowg1;
                        const bool km = (cl < 32) ? ((mb0 >> cl) & 1u)
                                                  : ((mb1 >> (cl - 32)) & 1u);
                        const bool ok = (kg <= row) && km;
                        sc[j][e] = ok ? sc[j][e] : -1e30f;
                    }
                }
            }

            // online softmax (base-2)
            float rm0 = -1e30f, rm1 = -1e30f;
            #pragma unroll
            for (int j = 0; j < 8; ++j) {
                rm0 = fmaxf(rm0, fmaxf(sc[j][0], sc[j][1]));
                rm1 = fmaxf(rm1, fmaxf(sc[j][2], sc[j][3]));
            }
            rm0 = fmaxf(rm0, __shfl_xor_sync(0xffffffffu, rm0, 1));
            rm0 = fmaxf(rm0, __shfl_xor_sync(0xffffffffu, rm0, 2));
            rm1 = fmaxf(rm1, __shfl_xor_sync(0xffffffffu, rm1, 1));
            rm1 = fmaxf(rm1, __shfl_xor_sync(0xffffffffu, rm1, 2));
            const float mn0 = fmaxf(m0, rm0), mn1 = fmaxf(m1, rm1);
            const float al0 = exp2f(m0 - mn0), al1 = exp2f(m1 - mn1);
            float s0 = 0.f, s1 = 0.f;
            #pragma unroll
            for (int j = 0; j < 8; ++j) {
                sc[j][0] = exp2f(sc[j][0] - mn0);
                sc[j][1] = exp2f(sc[j][1] - mn0);
                sc[j][2] = exp2f(sc[j][2] - mn1);
                sc[j][3] = exp2f(sc[j][3] - mn1);
                s0 += sc[j][0] + sc[j][1];
                s1 += sc[j][2] + sc[j][3];
            }
            s0 += __shfl_xor_sync(0xffffffffu, s0, 1);
            s0 += __shfl_xor_sync(0xffffffffu, s0, 2);
            s1 += __shfl_xor_sync(0xffffffffu, s1, 1);
            s1 += __shfl_xor_sync(0xffffffffu, s1, 2);
            l0 = l0 * al0 + s0;  m0 = mn0;
            l1 = l1 * al1 + s1;  m1 = mn1;
            #pragma unroll
            for (int j = 0; j < 8; ++j) {
                o[j][0] *= al0; o[j][1] *= al0;
                o[j][2] *= al1; o[j][3] *= al1;
            }

            // O += P @ V
            #pragma unroll
            for (int ks = 0; ks < 4; ++ks) {
                uint32_t pa[4];
                pa[0] = pack2(sc[2*ks  ][0], sc[2*ks  ][1]);
                pa[1] = pack2(sc[2*ks  ][2], sc[2*ks  ][3]);
                pa[2] = pack2(sc[2*ks+1][0], sc[2*ks+1][1]);
                pa[3] = pack2(sc[2*ks+1][2], sc[2*ks+1][3]);
                #pragma unroll
                for (int jj = 0; jj < 4; ++jj) {
                    uint32_t bq[4];
                    ldsm4t(bq, vs_u + ((ks*16 + lrow)*KVS + jj*16 + lkh)*2);
                    mma_f16(o[jj*2  ], pa, bq[0], bq[1]);
                    mma_f16(o[jj*2+1], pa, bq[2], bq[3]);
                }
            }

            // issue next load into stage (kt+2)%3 — last read at iter kt-1,
            // separated by this iteration's top barrier
            if (kt + 2 <= qt) load_kv(kt + 2, (kt + 2) % KV_STAGES);
            cp_commit();
        }

        const float i0 = 1.f / l0, i1 = 1.f / l1;
        __half* Ob = O + ((size_t)(b*Sn + qt*64 + wid*16))*Dn + h*DHn;
        #pragma unroll
        for (int j = 0; j < 8; ++j) {
            *(uint32_t*)&Ob[(size_t)(g    )*Dn + j*8 + t*2] = pack2(o[j][0]*i0, o[j][1]*i0);
            *(uint32_t*)&Ob[(size_t)(g + 8)*Dn + j*8 + t*2] = pack2(o[j][2]*i1, o[j][3]*i1);
        }
        __syncthreads();   // ring reused next phase
    }
}

// ==================== launch ====================
extern "C" void kernel_launch(void* const* d_in, const int* in_sizes, int n_in,
                              void* d_out, int out_size) {
    const float* x     = (const float*)d_in[0];
    const int*   amask = (const int*)  d_in[1];
    const float* Wq    = (const float*)d_in[2];
    const float* Wk    = (const float*)d_in[3];
    const float* Wv    = (const float*)d_in[4];
    const float* Wo    = (const float*)d_in[5];
    const float* W1    = (const float*)d_in[6];
    const float* W2    = (const float*)d_in[7];
    const float* gamma1= (const float*)d_in[8];
    const float* beta1 = (const float*)d_in[9];
    const float* gamma2= (const float*)d_in[10];
    const float* beta2 = (const float*)d_in[11];
    float* out = (float*)d_out;

    __half *xn1, *q, *k, *v, *attn, *xn2, *glu, *wh;
    float *x1;
    cudaGetSymbolAddress((void**)&xn1,  g_xn1);
    cudaGetSymbolAddress((void**)&q,    g_q);
    cudaGetSymbolAddress((void**)&k,    g_k);
    cudaGetSymbolAddress((void**)&v,    g_v);
    cudaGetSymbolAddress((void**)&attn, g_attn);
    cudaGetSymbolAddress((void**)&x1,   g_x1);
    cudaGetSymbolAddress((void**)&xn2,  g_xn2);
    cudaGetSymbolAddress((void**)&glu,  g_glu);
    cudaGetSymbolAddress((void**)&wh,   g_wh);

    cudaFuncSetAttribute(attn_f16, cudaFuncAttributeMaxDynamicSharedMemorySize, ATTN_SMEM);
    cudaFuncSetAttribute(gemm_qkv, cudaFuncAttributeMaxDynamicSharedMemorySize, GT_SMEM);
    cudaFuncSetAttribute((const void*)gemm_k<0,true>,  cudaFuncAttributeMaxDynamicSharedMemorySize, GT_SMEM);
    cudaFuncSetAttribute((const void*)gemm_k<2,false>, cudaFuncAttributeMaxDynamicSharedMemorySize, GT_SMEM);

    // 0. fused weight convert+transpose (W1 col-interleaved)
    cvtw_all<<<10240, 256>>>(Wq, Wk, Wv, Wo, W1, W2, wh);

    // 1. LN1 -> fp16
    ln_kernel<<<Mn, 256>>>(x, gamma1, beta1, xn1);

    // 2. fused Q,K,V projections -> fp16 (q pre-scaled for exp2 softmax)
    dim3 gQKV(Dn/BN, Mn/BM, 3);
    gemm_qkv<<<gQKV, 256, GT_SMEM>>>(xn1, wh, q, k, v);

    // 3. causal attention -> fp16 (balanced qt pairs, 3-stage KV ring)
    dim3 gA(NQT/2, Hn, Bn);
    attn_f16<<<gA, 128, ATTN_SMEM>>>(q, k, v, amask, attn);

    // 4. output projection + residual -> fp32 x1
    dim3 gD(Dn/BN, Mn/BM);
    gemm_k<0,true><<<gD, 256, GT_SMEM>>>(attn, wh + WOFF_O, x, x1, Mn, Dn, Dn);

    // 5. LN2 -> fp16
    ln_kernel<<<Mn, 256>>>(x1, gamma2, beta2, xn2);

    // 6. W1 + GLU fused -> fp16 glu [Mn, 2048]
    dim3 gF(DFF/BN, Mn/BM);
    gemm_k<2,false><<<gF, 256, GT_SMEM>>>(xn2, wh + WOFF_1, nullptr, glu, Mn, DFF, Dn);

    // 7. W2 + residual -> fp32 out
    gemm_k<0,true><<<gD, 256, GT_SMEM>>>(glu, wh + WOFF_2, x1, out, Mn, Dn, DG);
}

// round 15
// speedup vs baseline: 1.0292x; 1.0182x over previous
#include <cuda_runtime.h>
#include <cuda_fp16.h>
#include <math.h>
#include <stdint.h>

// Problem constants
#define Bn   2
#define Sn   2048
#define Dn   1024
#define Hn   16
#define DHn  64
#define Mn   (Bn*Sn)          // 4096 rows
#define DFF  (4*Dn)           // 4096
#define DG   (2*Dn)           // 2048
#define EPSV 1e-5f

// -------------------- scratch (device globals; no allocation) --------------------
__device__ __half g_xn1 [Mn*Dn];
__device__ __half g_q   [Mn*Dn];
__device__ __half g_k   [Mn*Dn];
__device__ __half g_v   [Mn*Dn];
__device__ __half g_attn[Mn*Dn];
__device__ __half g_x1  [Mn*Dn];     // fp16 now
__device__ __half g_xn2 [Mn*Dn];
__device__ __half g_glu [Mn*DG];
__device__ __half g_wh  [10485760];  // fp16 TRANSPOSED weights [N][K] (W1 col-interleaved)

#define WOFF_Q  0
#define WOFF_K  1048576
#define WOFF_V  2097152
#define WOFF_O  3145728
#define WOFF_1  4194304
#define WOFF_2  8388608

// -------------------- helpers --------------------
__device__ __forceinline__ void mma_f16(float c[4], const uint32_t a[4],
                                        uint32_t b0, uint32_t b1) {
    asm volatile(
        "mma.sync.aligned.m16n8k16.row.col.f32.f16.f16.f32 "
        "{%0,%1,%2,%3}, {%4,%5,%6,%7}, {%8,%9}, {%0,%1,%2,%3};"
        : "+f"(c[0]), "+f"(c[1]), "+f"(c[2]), "+f"(c[3])
        : "r"(a[0]), "r"(a[1]), "r"(a[2]), "r"(a[3]), "r"(b0), "r"(b1));
}

__device__ __forceinline__ uint32_t smem_u32(const void* p) {
    uint32_t a;
    asm("{ .reg .u64 t; cvta.to.shared.u64 t, %1; cvt.u32.u64 %0, t; }"
        : "=r"(a) : "l"(p));
    return a;
}

__device__ __forceinline__ void ldsm4(uint32_t r[4], uint32_t addr) {
    asm volatile("ldmatrix.sync.aligned.m8n8.x4.shared.b16 {%0,%1,%2,%3}, [%4];"
        : "=r"(r[0]), "=r"(r[1]), "=r"(r[2]), "=r"(r[3]) : "r"(addr));
}
__device__ __forceinline__ void ldsm4t(uint32_t r[4], uint32_t addr) {
    asm volatile("ldmatrix.sync.aligned.m8n8.x4.trans.shared.b16 {%0,%1,%2,%3}, [%4];"
        : "=r"(r[0]), "=r"(r[1]), "=r"(r[2]), "=r"(r[3]) : "r"(addr));
}

__device__ __forceinline__ void cp16(uint32_t dst, const void* src) {
    asm volatile("cp.async.cg.shared.global [%0], [%1], 16;" :: "r"(dst), "l"(src) : "memory");
}
__device__ __forceinline__ void cp_commit() { asm volatile("cp.async.commit_group;" ::: "memory"); }
template<int N>
__device__ __forceinline__ void cp_wait() { asm volatile("cp.async.wait_group %0;" :: "n"(N) : "memory"); }

__device__ __forceinline__ uint32_t pack2(float x, float y) {
    __half2 h = __floats2half2_rn(x, y);
    return *(uint32_t*)&h;
}

// ==================== fused weight cvt fp16 + transpose (ONE launch) ====================
// W1 destination rows are column-interleaved: src col j -> dst row 2j (j<2048) / 2(j-2048)+1
__global__ __launch_bounds__(256) void cvtw_all(
    const float* __restrict__ Wq, const float* __restrict__ Wk,
    const float* __restrict__ Wv, const float* __restrict__ Wo,
    const float* __restrict__ W1, const float* __restrict__ W2,
    __half* __restrict__ wh)
{
    __shared__ float tile[32][33];
    const int bid = blockIdx.x;
    const float* src; __half* dst; int K, N, t_;
    bool perm = false;
    if (bid < 4096) {
        const int m = bid >> 10; t_ = bid & 1023;
        src = (m == 0) ? Wq : (m == 1) ? Wk : (m == 2) ? Wv : Wo;
        dst = wh + (size_t)m * 1048576;
        K = 1024; N = 1024;
    } else if (bid < 8192) {
        t_ = bid - 4096; src = W1; dst = wh + WOFF_1; K = 1024; N = 4096; perm = true;
    } else {
        t_ = bid - 8192; src = W2; dst = wh + WOFF_2; K = 2048; N = 1024;
    }
    const int ntx = N >> 5;
    const int bn = (t_ % ntx) * 32, bk = (t_ / ntx) * 32;
    const int tx = threadIdx.x & 31, ty = threadIdx.x >> 5;
    #pragma unroll
    for (int r = 0; r < 4; ++r)
        tile[ty + 8*r][tx] = src[(size_t)(bk + ty + 8*r) * N + bn + tx];
    __syncthreads();
    #pragma unroll
    for (int r = 0; r < 4; ++r) {
        int n = bn + ty + 8*r;
        if (perm) n = (n < 2048) ? 2*n : 2*(n - 2048) + 1;
        dst[(size_t)n * K + bk + tx] = __float2half_rn(tile[tx][ty + 8*r]);
    }
}

// ==================== LayerNorm: fp32 in -> fp16 out ====================
__global__ __launch_bounds__(256) void ln_kernel(const float* __restrict__ x,
                                                 const float* __restrict__ gamma,
                                                 const float* __restrict__ beta,
                                                 __half* __restrict__ out) {
    const int row = blockIdx.x;
    const int tid = threadIdx.x;
    const float4* xr = (const float4*)(x + (size_t)row * Dn);
    float4 v = xr[tid];
    float s  = v.x + v.y + v.z + v.w;
    float ss = v.x*v.x + v.y*v.y + v.z*v.z + v.w*v.w;
    #pragma unroll
    for (int off = 16; off > 0; off >>= 1) {
        s  += __shfl_xor_sync(0xffffffffu, s,  off);
        ss += __shfl_xor_sync(0xffffffffu, ss, off);
    }
    __shared__ float red[2][8];
    const int wid = tid >> 5, lid = tid & 31;
    if (lid == 0) { red[0][wid] = s; red[1][wid] = ss; }
    __syncthreads();
    __shared__ float smu, srstd;
    if (tid == 0) {
        float ts = 0.f, tss = 0.f;
        #pragma unroll
        for (int i = 0; i < 8; ++i) { ts += red[0][i]; tss += red[1][i]; }
        float mu  = ts * (1.0f / Dn);
        float var = tss * (1.0f / Dn) - mu * mu;
        smu = mu; srstd = rsqrtf(var + EPSV);
    }
    __syncthreads();
    const float mu = smu, rstd = srstd;
    float4 g = ((const float4*)gamma)[tid];
    float4 b = ((const float4*)beta)[tid];
    uint2 u;
    u.x = pack2(g.x * (v.x - mu) * rstd + b.x, g.y * (v.y - mu) * rstd + b.y);
    u.y = pack2(g.z * (v.z - mu) * rstd + b.z, g.w * (v.w - mu) * rstd + b.w);
    ((uint2*)(out + (size_t)row * Dn))[tid] = u;
}

// LayerNorm reading fp16 input (for x1)
__global__ __launch_bounds__(256) void ln_kernel_h(const __half* __restrict__ x,
                                                   const float* __restrict__ gamma,
                                                   const float* __restrict__ beta,
                                                   __half* __restrict__ out) {
    const int row = blockIdx.x;
    const int tid = threadIdx.x;
    uint2 xr = ((const uint2*)(x + (size_t)row * Dn))[tid];
    float2 a0 = __half22float2(*(__half2*)&xr.x);
    float2 a1 = __half22float2(*(__half2*)&xr.y);
    float s  = a0.x + a0.y + a1.x + a1.y;
    float ss = a0.x*a0.x + a0.y*a0.y + a1.x*a1.x + a1.y*a1.y;
    #pragma unroll
    for (int off = 16; off > 0; off >>= 1) {
        s  += __shfl_xor_sync(0xffffffffu, s,  off);
        ss += __shfl_xor_sync(0xffffffffu, ss, off);
    }
    __shared__ float red[2][8];
    const int wid = tid >> 5, lid = tid & 31;
    if (lid == 0) { red[0][wid] = s; red[1][wid] = ss; }
    __syncthreads();
    __shared__ float smu, srstd;
    if (tid == 0) {
        float ts = 0.f, tss = 0.f;
        #pragma unroll
        for (int i = 0; i < 8; ++i) { ts += red[0][i]; tss += red[1][i]; }
        float mu  = ts * (1.0f / Dn);
        float var = tss * (1.0f / Dn) - mu * mu;
        smu = mu; srstd = rsqrtf(var + EPSV);
    }
    __syncthreads();
    const float mu = smu, rstd = srstd;
    float4 g = ((const float4*)gamma)[tid];
    float4 b = ((const float4*)beta)[tid];
    uint2 u;
    u.x = pack2(g.x * (a0.x - mu) * rstd + b.x, g.y * (a0.y - mu) * rstd + b.y);
    u.y = pack2(g.z * (a1.x - mu) * rstd + b.z, g.w * (a1.y - mu) * rstd + b.w);
    ((uint2*)(out + (size_t)row * Dn))[tid] = u;
}

// ==================== FP16 tensor GEMM, cp.async 3-stage + ldmatrix (R12 config) ====================
#define BM 128
#define BN 128
#define BKH 32
#define STAGES 3
#define TSH 56
#define TILE_BYTES (128*TSH*2)
#define GT_SMEM (STAGES*2*TILE_BYTES)   // 86016

// MODE: 0 = fp32 out + fp32 resid, 1 = fp16 out (scaled), 2 = GLU epilogue,
//       3 = fp16 out + fp16 resid (x1 = x + attn@Wo), 4 = fp32 out + fp16 resid (final)
template<int MODE>
__device__ __forceinline__ void gemm_body(
    const __half* __restrict__ A, const __half* __restrict__ Bt,
    const void* __restrict__ Rv, void* __restrict__ Cv,
    int M_, int N_, int K_, float oscale)
{
    extern __shared__ char smem[];
    const uint32_t sbase = smem_u32(smem);

    const int tid = threadIdx.x;
    const int bx = blockIdx.x, by = blockIdx.y;
    const int wid = tid >> 5, lane = tid & 31;
    const int wm = (wid >> 2) * 64, wn = (wid & 3) * 32;

    const int ld_row = tid >> 2;
    const int ld_ch  = tid & 3;

    const int lrow = lane & 15;
    const int lkh  = (lane >> 4) * 8;

    const int nt = K_ >> 5;
    int kload = 0;

    auto issue = [&](int kt, int st) {
        const uint32_t da = sbase + st*(2*TILE_BYTES);
        const uint32_t db = da + TILE_BYTES;
        cp16(da + (ld_row     )*(TSH*2) + ld_ch*16,
             &A[(size_t)(by*BM + ld_row     )*K_ + kt*BKH + ld_ch*8]);
        cp16(da + (ld_row + 64)*(TSH*2) + ld_ch*16,
             &A[(size_t)(by*BM + ld_row + 64)*K_ + kt*BKH + ld_ch*8]);
        cp16(db + (ld_row     )*(TSH*2) + ld_ch*16,
             &Bt[(size_t)(bx*BN + ld_row     )*K_ + kt*BKH + ld_ch*8]);
        cp16(db + (ld_row + 64)*(TSH*2) + ld_ch*16,
             &Bt[(size_t)(bx*BN + ld_row + 64)*K_ + kt*BKH + ld_ch*8]);
    };

    float acc[4][4][4];
    #pragma unroll
    for (int i = 0; i < 4; ++i)
        #pragma unroll
        for (int j = 0; j < 4; ++j)
            #pragma unroll
            for (int e = 0; e < 4; ++e) acc[i][j][e] = 0.f;

    issue(0, 0); cp_commit();
    issue(1, 1); cp_commit();
    kload = 2;

    int st = 0;
    for (int kt = 0; kt < nt; ++kt) {
        cp_wait<STAGES-2>();
        __syncthreads();
        const uint32_t sa = sbase + st*(2*TILE_BYTES);
        const uint32_t sb = sa + TILE_BYTES;
        #pragma unroll
        for (int kk = 0; kk < 2; ++kk) {
            uint32_t afr[4][4], bq[2][4];
            #pragma unroll
            for (int i = 0; i < 4; ++i)
                ldsm4(afr[i], sa + ((wm + i*16 + lrow)*TSH + kk*16 + lkh)*2);
            #pragma unroll
            for (int jj = 0; jj < 2; ++jj)
                ldsm4(bq[jj], sb + ((wn + jj*16 + lrow)*TSH + kk*16 + lkh)*2);
            #pragma unroll
            for (int i = 0; i < 4; ++i) {
                #pragma unroll
                for (int jj = 0; jj < 2; ++jj) {
                    mma_f16(acc[i][jj*2  ], afr[i], bq[jj][0], bq[jj][2]);
                    mma_f16(acc[i][jj*2+1], afr[i], bq[jj][1], bq[jj][3]);
                }
            }
        }
        if (kload < nt) {
            issue(kload, (st + 2 >= STAGES) ? st + 2 - STAGES : st + 2);
            ++kload;
        }
        cp_commit();
        if (++st == STAGES) st = 0;
    }

    // epilogue
    const int eg = lane >> 2, et = lane & 3;
    #pragma unroll
    for (int i = 0; i < 4; ++i) {
        const int row0 = by*BM + wm + i*16 + eg;
        const int row1 = row0 + 8;
        #pragma unroll
        for (int j = 0; j < 4; ++j) {
            const int col = bx*BN + wn + j*8 + et*2;
            if (MODE == 2) {
                __half* C = (__half*)Cv;
                const int colh = col >> 1;
                const int No = N_ >> 1;
                float g0 = acc[i][j][0] / (1.f + __expf(-acc[i][j][1]));
                float g1 = acc[i][j][2] / (1.f + __expf(-acc[i][j][3]));
                C[(size_t)row0*No + colh] = __float2half_rn(g0);
                C[(size_t)row1*No + colh] = __float2half_rn(g1);
            } else if (MODE == 1) {
                __half* C = (__half*)Cv;
                *(uint32_t*)&C[(size_t)row0*N_ + col] =
                    pack2(acc[i][j][0]*oscale, acc[i][j][1]*oscale);
                *(uint32_t*)&C[(size_t)row1*N_ + col] =
                    pack2(acc[i][j][2]*oscale, acc[i][j][3]*oscale);
            } else if (MODE == 3) {
                // x1 = x(fp32) + acc  -> fp16 out
                const float* R = (const float*)Rv;
                __half* C = (__half*)Cv;
                float2 r0 = *(const float2*)&R[(size_t)row0*N_ + col];
                float2 r1 = *(const float2*)&R[(size_t)row1*N_ + col];
                *(uint32_t*)&C[(size_t)row0*N_ + col] =
                    pack2(acc[i][j][0] + r0.x, acc[i][j][1] + r0.y);
                *(uint32_t*)&C[(size_t)row1*N_ + col] =
                    pack2(acc[i][j][2] + r1.x, acc[i][j][3] + r1.y);
            } else if (MODE == 4) {
                // out = x1(fp16) + acc -> fp32 out
                const __half* R = (const __half*)Rv;
                float* C = (float*)Cv;
                uint32_t r0u = *(const uint32_t*)&R[(size_t)row0*N_ + col];
                uint32_t r1u = *(const uint32_t*)&R[(size_t)row1*N_ + col];
                float2 r0 = __half22float2(*(__half2*)&r0u);
                float2 r1 = __half22float2(*(__half2*)&r1u);
                float2 v0 = { acc[i][j][0] + r0.x, acc[i][j][1] + r0.y };
                float2 v1 = { acc[i][j][2] + r1.x, acc[i][j][3] + r1.y };
                *(float2*)&C[(size_t)row0*N_ + col] = v0;
                *(float2*)&C[(size_t)row1*N_ + col] = v1;
            } else {
                const float* R = (const float*)Rv;
                float* C = (float*)Cv;
                float2 v0 = { acc[i][j][0], acc[i][j][1] };
                float2 v1 = { acc[i][j][2], acc[i][j][3] };
                if (Rv) {
                    float2 r0 = *(const float2*)&R[(size_t)row0*N_ + col];
                    float2 r1 = *(const float2*)&R[(size_t)row1*N_ + col];
                    v0.x += r0.x; v0.y += r0.y;
                    v1.x += r1.x; v1.y += r1.y;
                }
                *(float2*)&C[(size_t)row0*N_ + col] = v0;
                *(float2*)&C[(size_t)row1*N_ + col] = v1;
            }
        }
    }
}

template<int MODE>
__global__ __launch_bounds__(256, 2) void gemm_k(
    const __half* __restrict__ A, const __half* __restrict__ Bt,
    const void* __restrict__ Rv, void* __restrict__ Cv,
    int M_, int N_, int K_)
{
    gemm_body<MODE>(A, Bt, Rv, Cv, M_, N_, K_, 1.0f);
}

// fused QKV; q output pre-scaled by (1/sqrt(DH)) * log2(e) for exp2-based softmax
#define QSCALE (0.125f * 1.4426950408889634f)
__global__ __launch_bounds__(256, 2) void gemm_qkv(
    const __half* __restrict__ A, const __half* __restrict__ W,
    __half* __restrict__ q, __half* __restrict__ k, __half* __restrict__ v)
{
    const int z = blockIdx.z;
    const __half* Bt = W + (z == 0 ? WOFF_Q : z == 1 ? WOFF_K : WOFF_V);
    __half* C = (z == 0) ? q : (z == 1) ? k : v;
    gemm_body<1>(A, Bt, nullptr, C, Mn, Dn, Dn, z == 0 ? QSCALE : 1.0f);
}

// ==================== causal flash attention: R12 config (2-stage, qt-pairing, exp2) ====================
#define KVS 72
#define KV_STAGE_BYTES (2*64*KVS*2)
#define ATTN_SMEM (2*KV_STAGE_BYTES)      // 36864
#define NQT (Sn/64)                       // 32

__global__ __launch_bounds__(128, 3) void attn_f16(
    const __half* __restrict__ Q, const __half* __restrict__ K,
    const __half* __restrict__ V, const int* __restrict__ mask,
    __half* __restrict__ O) {
    extern __shared__ __half smh[];
    const uint32_t sm0 = smem_u32(smh);
    __shared__ uint32_t mbits[2][2];

    const int pair = blockIdx.x;          // 0..15
    const int h = blockIdx.y, b = blockIdx.z;
    const int tid = threadIdx.x;
    const int wid = tid >> 5, lane = tid & 31;
    const int g = lane >> 2, t = lane & 3;
    const int lrow = lane & 15;
    const int lkh  = (lane >> 4) * 8;

    #pragma unroll
    for (int ph = 0; ph < 2; ++ph) {
        const int qt = (ph == 0) ? (NQT - 1 - pair) : pair;   // heavy first

        const __half* Qb = Q + ((size_t)(b*Sn + qt*64 + wid*16))*Dn + h*DHn;
        uint32_t qa[4][4];
        #pragma unroll
        for (int ks = 0; ks < 4; ++ks) {
            qa[ks][0] = *(const uint32_t*)&Qb[(size_t)(g    )*Dn + ks*16 + 2*t];
            qa[ks][1] = *(const uint32_t*)&Qb[(size_t)(g + 8)*Dn + ks*16 + 2*t];
            qa[ks][2] = *(const uint32_t*)&Qb[(size_t)(g    )*Dn + ks*16 + 8 + 2*t];
            qa[ks][3] = *(const uint32_t*)&Qb[(size_t)(g + 8)*Dn + ks*16 + 8 + 2*t];
        }

        auto load_kv = [&](int kt, int st) {
            const uint32_t ks_u = sm0 + st*KV_STAGE_BYTES;
            const uint32_t vs_u = ks_u + 64*KVS*2;
            const __half* Kb = K + (size_t)(b*Sn + kt*64)*Dn + h*DHn;
            const __half* Vb = V + (size_t)(b*Sn + kt*64)*Dn + h*DHn;
            #pragma unroll
            for (int c = 0; c < 4; ++c) {
                const int idx = tid + c*128;
                const int rr = idx >> 3, ch = idx & 7;
                cp16(ks_u + rr*(KVS*2) + ch*16, Kb + (size_t)rr*Dn + ch*8);
                cp16(vs_u + rr*(KVS*2) + ch*16, Vb + (size_t)rr*Dn + ch*8);
            }
            if (tid < 64) {
                const int val = mask[b*Sn + kt*64 + tid];
                const unsigned bal = __ballot_sync(0xffffffffu, val != 0);
                if ((tid & 31) == 0) mbits[st][tid >> 5] = bal;
            }
        };

        float o[8][4];
        #pragma unroll
        for (int j = 0; j < 8; ++j)
            #pragma unroll
            for (int e = 0; e < 4; ++e) o[j][e] = 0.f;
        float m0 = -1e30f, m1 = -1e30f, l0 = 0.f, l1 = 0.f;

        const int rowg0 = qt*64 + wid*16 + g;
        const int rowg1 = rowg0 + 8;

        load_kv(0, 0); cp_commit();
        if (qt >= 1) load_kv(1, 1);
        cp_commit();

        int buf = 0;
        for (int kt = 0; kt <= qt; ++kt) {
            cp_wait<1>();
            __syncthreads();
            const uint32_t ks_u = sm0 + buf*KV_STAGE_BYTES;
            const uint32_t vs_u = ks_u + 64*KVS*2;

            float sc[8][4];
            #pragma unroll
            for (int j = 0; j < 8; ++j)
                #pragma unroll
                for (int e = 0; e < 4; ++e) sc[j][e] = 0.f;
            #pragma unroll
            for (int ks = 0; ks < 4; ++ks) {
                #pragma unroll
                for (int jj = 0; jj < 4; ++jj) {
                    uint32_t bq[4];
                    ldsm4(bq, ks_u + ((jj*16 + lrow)*KVS + ks*16 + lkh)*2);
                    mma_f16(sc[jj*2  ], qa[ks], bq[0], bq[2]);
                    mma_f16(sc[jj*2+1], qa[ks], bq[1], bq[3]);
                }
            }

            const uint32_t mb0 = mbits[buf][0], mb1 = mbits[buf][1];
            const bool need_mask = (kt == qt) || ((mb0 & mb1) != 0xffffffffu);
            if (need_mask) {
                #pragma unroll
                for (int j = 0; j < 8; ++j) {
                    #pragma unroll
                    for (int e = 0; e < 4; ++e) {
                        const int cl  = j*8 + t*2 + (e & 1);
                        const int kg  = kt*64 + cl;
                        const int row = (e < 2) ? rowg0 : rowg1;
                        const bool km = (cl < 32) ? ((mb0 >> cl) & 1u)
                                                  : ((mb1 >> (cl - 32)) & 1u);
                        const bool ok = (kg <= row) && km;
                        sc[j][e] = ok ? sc[j][e] : -1e30f;
                    }
                }
            }

            float rm0 = -1e30f, rm1 = -1e30f;
            #pragma unroll
            for (int j = 0; j < 8; ++j) {
                rm0 = fmaxf(rm0, fmaxf(sc[j][0], sc[j][1]));
                rm1 = fmaxf(rm1, fmaxf(sc[j][2], sc[j][3]));
            }
            rm0 = fmaxf(rm0, __shfl_xor_sync(0xffffffffu, rm0, 1));
            rm0 = fmaxf(rm0, __shfl_xor_sync(0xffffffffu, rm0, 2));
            rm1 = fmaxf(rm1, __shfl_xor_sync(0xffffffffu, rm1, 1));
            rm1 = fmaxf(rm1, __shfl_xor_sync(0xffffffffu, rm1, 2));
            const float mn0 = fmaxf(m0, rm0), mn1 = fmaxf(m1, rm1);
            const float al0 = exp2f(m0 - mn0), al1 = exp2f(m1 - mn1);
            float s0 = 0.f, s1 = 0.f;
            #pragma unroll
            for (int j = 0; j < 8; ++j) {
                sc[j][0] = exp2f(sc[j][0] - mn0);
                sc[j][1] = exp2f(sc[j][1] - mn0);
                sc[j][2] = exp2f(sc[j][2] - mn1);
                sc[j][3] = exp2f(sc[j][3] - mn1);
                s0 += sc[j][0] + sc[j][1];
                s1 += sc[j][2] + sc[j][3];
            }
            s0 += __shfl_xor_sync(0xffffffffu, s0, 1);
            s0 += __shfl_xor_sync(0xffffffffu, s0, 2);
            s1 += __shfl_xor_sync(0xffffffffu, s1, 1);
            s1 += __shfl_xor_sync(0xffffffffu, s1, 2);
            l0 = l0 * al0 + s0;  m0 = mn0;
            l1 = l1 * al1 + s1;  m1 = mn1;
            #pragma unroll
            for (int j = 0; j < 8; ++j) {
                o[j][0] *= al0; o[j][1] *= al0;
                o[j][2] *= al1; o[j][3] *= al1;
            }

            #pragma unroll
            for (int ks = 0; ks < 4; ++ks) {
                uint32_t pa[4];
                pa[0] = pack2(sc[2*ks  ][0], sc[2*ks  ][1]);
                pa[1] = pack2(sc[2*ks  ][2], sc[2*ks  ][3]);
                pa[2] = pack2(sc[2*ks+1][0], sc[2*ks+1][1]);
                pa[3] = pack2(sc[2*ks+1][2], sc[2*ks+1][3]);
                #pragma unroll
                for (int jj = 0; jj < 4; ++jj) {
                    uint32_t bq[4];
                    ldsm4t(bq, vs_u + ((ks*16 + lrow)*KVS + jj*16 + lkh)*2);
                    mma_f16(o[jj*2  ], pa, bq[0], bq[1]);
                    mma_f16(o[jj*2+1], pa, bq[2], bq[3]);
                }
            }

            __syncthreads();
            if (kt + 2 <= qt) load_kv(kt + 2, buf);
            cp_commit();
            buf ^= 1;
        }

        const float i0 = 1.f / l0, i1 = 1.f / l1;
        __half* Ob = O + ((size_t)(b*Sn + qt*64 + wid*16))*Dn + h*DHn;
        #pragma unroll
        for (int j = 0; j < 8; ++j) {
            *(uint32_t*)&Ob[(size_t)(g    )*Dn + j*8 + t*2] = pack2(o[j][0]*i0, o[j][1]*i0);
            *(uint32_t*)&Ob[(size_t)(g + 8)*Dn + j*8 + t*2] = pack2(o[j][2]*i1, o[j][3]*i1);
        }
        __syncthreads();
    }
}

// ==================== launch ====================
extern "C" void kernel_launch(void* const* d_in, const int* in_sizes, int n_in,
                              void* d_out, int out_size) {
    const float* x     = (const float*)d_in[0];
    const int*   amask = (const int*)  d_in[1];
    const float* Wq    = (const float*)d_in[2];
    const float* Wk    = (const float*)d_in[3];
    const float* Wv    = (const float*)d_in[4];
    const float* Wo    = (const float*)d_in[5];
    const float* W1    = (const float*)d_in[6];
    const float* W2    = (const float*)d_in[7];
    const float* gamma1= (const float*)d_in[8];
    const float* beta1 = (const float*)d_in[9];
    const float* gamma2= (const float*)d_in[10];
    const float* beta2 = (const float*)d_in[11];
    float* out = (float*)d_out;

    __half *xn1, *q, *k, *v, *attn, *x1, *xn2, *glu, *wh;
    cudaGetSymbolAddress((void**)&xn1,  g_xn1);
    cudaGetSymbolAddress((void**)&q,    g_q);
    cudaGetSymbolAddress((void**)&k,    g_k);
    cudaGetSymbolAddress((void**)&v,    g_v);
    cudaGetSymbolAddress((void**)&attn, g_attn);
    cudaGetSymbolAddress((void**)&x1,   g_x1);
    cudaGetSymbolAddress((void**)&xn2,  g_xn2);
    cudaGetSymbolAddress((void**)&glu,  g_glu);
    cudaGetSymbolAddress((void**)&wh,   g_wh);

    cudaFuncSetAttribute(attn_f16, cudaFuncAttributeMaxDynamicSharedMemorySize, ATTN_SMEM);
    cudaFuncSetAttribute(gemm_qkv, cudaFuncAttributeMaxDynamicSharedMemorySize, GT_SMEM);
    cudaFuncSetAttribute((const void*)gemm_k<2>, cudaFuncAttributeMaxDynamicSharedMemorySize, GT_SMEM);
    cudaFuncSetAttribute((const void*)gemm_k<3>, cudaFuncAttributeMaxDynamicSharedMemorySize, GT_SMEM);
    cudaFuncSetAttribute((const void*)gemm_k<4>, cudaFuncAttributeMaxDynamicSharedMemorySize, GT_SMEM);

    // 0. fused weight convert+transpose (W1 col-interleaved)
    cvtw_all<<<10240, 256>>>(Wq, Wk, Wv, Wo, W1, W2, wh);

    // 1. LN1 -> fp16
    ln_kernel<<<Mn, 256>>>(x, gamma1, beta1, xn1);

    // 2. fused Q,K,V projections -> fp16 (q pre-scaled for exp2 softmax)
    dim3 gQKV(Dn/BN, Mn/BM, 3);
    gemm_qkv<<<gQKV, 256, GT_SMEM>>>(xn1, wh, q, k, v);

    // 3. causal attention -> fp16 (balanced qt pairs)
    dim3 gA(NQT/2, Hn, Bn);
    attn_f16<<<gA, 128, ATTN_SMEM>>>(q, k, v, amask, attn);

    // 4. x1 = x + attn@Wo -> fp16
    dim3 gD(Dn/BN, Mn/BM);
    gemm_k<3><<<gD, 256, GT_SMEM>>>(attn, wh + WOFF_O, x, x1, Mn, Dn, Dn);

    // 5. LN2 (fp16 in) -> fp16
    ln_kernel_h<<<Mn, 256>>>(x1, gamma2, beta2, xn2);

    // 6. W1 + GLU fused -> fp16 glu [Mn, 2048]
    dim3 gF(DFF/BN, Mn/BM);
    gemm_k<2><<<gF, 256, GT_SMEM>>>(xn2, wh + WOFF_1, nullptr, glu, Mn, DFF, Dn);

    // 7. out = x1(fp16) + glu@W2 -> fp32
    gemm_k<4><<<gD, 256, GT_SMEM>>>(glu, wh + WOFF_2, x1, out, Mn, Dn, DG);
}

// round 16
// speedup vs baseline: 1.0329x; 1.0036x over previous
#include <cuda_runtime.h>
#include <cuda_fp16.h>
#include <math.h>
#include <stdint.h>

// Problem constants
#define Bn   2
#define Sn   2048
#define Dn   1024
#define Hn   16
#define DHn  64
#define Mn   (Bn*Sn)          // 4096 rows
#define DFF  (4*Dn)           // 4096
#define DG   (2*Dn)           // 2048
#define EPSV 1e-5f

// -------------------- scratch (device globals; no allocation) --------------------
__device__ __half g_xn1 [Mn*Dn];
__device__ __half g_q   [Mn*Dn];
__device__ __half g_k   [Mn*Dn];
__device__ __half g_v   [Mn*Dn];
__device__ __half g_attn[Mn*Dn];
__device__ __half g_x1  [Mn*Dn];
__device__ __half g_xn2 [Mn*Dn];
__device__ __half g_glu [Mn*DG];
__device__ __half g_wh  [10485760];  // fp16 TRANSPOSED weights [N][K] (W1 col-interleaved)

#define WOFF_Q  0
#define WOFF_K  1048576
#define WOFF_V  2097152
#define WOFF_O  3145728
#define WOFF_1  4194304
#define WOFF_2  8388608

// -------------------- helpers --------------------
__device__ __forceinline__ void mma_f16(float c[4], const uint32_t a[4],
                                        uint32_t b0, uint32_t b1) {
    asm volatile(
        "mma.sync.aligned.m16n8k16.row.col.f32.f16.f16.f32 "
        "{%0,%1,%2,%3}, {%4,%5,%6,%7}, {%8,%9}, {%0,%1,%2,%3};"
        : "+f"(c[0]), "+f"(c[1]), "+f"(c[2]), "+f"(c[3])
        : "r"(a[0]), "r"(a[1]), "r"(a[2]), "r"(a[3]), "r"(b0), "r"(b1));
}

__device__ __forceinline__ uint32_t smem_u32(const void* p) {
    uint32_t a;
    asm("{ .reg .u64 t; cvta.to.shared.u64 t, %1; cvt.u32.u64 %0, t; }"
        : "=r"(a) : "l"(p));
    return a;
}

__device__ __forceinline__ void ldsm4(uint32_t r[4], uint32_t addr) {
    asm volatile("ldmatrix.sync.aligned.m8n8.x4.shared.b16 {%0,%1,%2,%3}, [%4];"
        : "=r"(r[0]), "=r"(r[1]), "=r"(r[2]), "=r"(r[3]) : "r"(addr));
}
__device__ __forceinline__ void ldsm4t(uint32_t r[4], uint32_t addr) {
    asm volatile("ldmatrix.sync.aligned.m8n8.x4.trans.shared.b16 {%0,%1,%2,%3}, [%4];"
        : "=r"(r[0]), "=r"(r[1]), "=r"(r[2]), "=r"(r[3]) : "r"(addr));
}

__device__ __forceinline__ void cp16(uint32_t dst, const void* src) {
    asm volatile("cp.async.cg.shared.global [%0], [%1], 16;" :: "r"(dst), "l"(src) : "memory");
}
__device__ __forceinline__ void cp_commit() { asm volatile("cp.async.commit_group;" ::: "memory"); }
template<int N>
__device__ __forceinline__ void cp_wait() { asm volatile("cp.async.wait_group %0;" :: "n"(N) : "memory"); }

__device__ __forceinline__ uint32_t pack2(float x, float y) {
    __half2 h = __floats2half2_rn(x, y);
    return *(uint32_t*)&h;
}

// ==================== prep: weight cvt+transpose + LN1, ONE launch ====================
// blocks [0,10240): weight tiles (W1 col-interleaved). blocks [10240,14336): LN1 rows.
__global__ __launch_bounds__(256) void prep_all(
    const float* __restrict__ Wq, const float* __restrict__ Wk,
    const float* __restrict__ Wv, const float* __restrict__ Wo,
    const float* __restrict__ W1, const float* __restrict__ W2,
    __half* __restrict__ wh,
    const float* __restrict__ x, const float* __restrict__ gamma1,
    const float* __restrict__ beta1, __half* __restrict__ xn1)
{
    const int bid = blockIdx.x;
    const int tid = threadIdx.x;
    if (bid < 10240) {
        __shared__ float tile[32][33];
        const float* src; __half* dst; int K, N, t_;
        bool perm = false;
        if (bid < 4096) {
            const int m = bid >> 10; t_ = bid & 1023;
            src = (m == 0) ? Wq : (m == 1) ? Wk : (m == 2) ? Wv : Wo;
            dst = wh + (size_t)m * 1048576;
            K = 1024; N = 1024;
        } else if (bid < 8192) {
            t_ = bid - 4096; src = W1; dst = wh + WOFF_1; K = 1024; N = 4096; perm = true;
        } else {
            t_ = bid - 8192; src = W2; dst = wh + WOFF_2; K = 2048; N = 1024;
        }
        const int ntx = N >> 5;
        const int bn = (t_ % ntx) * 32, bk = (t_ / ntx) * 32;
        const int tx = tid & 31, ty = tid >> 5;
        #pragma unroll
        for (int r = 0; r < 4; ++r)
            tile[ty + 8*r][tx] = src[(size_t)(bk + ty + 8*r) * N + bn + tx];
        __syncthreads();
        #pragma unroll
        for (int r = 0; r < 4; ++r) {
            int n = bn + ty + 8*r;
            if (perm) n = (n < 2048) ? 2*n : 2*(n - 2048) + 1;
            dst[(size_t)n * K + bk + tx] = __float2half_rn(tile[tx][ty + 8*r]);
        }
    } else {
        // LN1 on row (bid - 10240)
        const int row = bid - 10240;
        const float4* xr = (const float4*)(x + (size_t)row * Dn);
        float4 v = xr[tid];
        float s  = v.x + v.y + v.z + v.w;
        float ss = v.x*v.x + v.y*v.y + v.z*v.z + v.w*v.w;
        #pragma unroll
        for (int off = 16; off > 0; off >>= 1) {
            s  += __shfl_xor_sync(0xffffffffu, s,  off);
            ss += __shfl_xor_sync(0xffffffffu, ss, off);
        }
        __shared__ float red[2][8];
        const int wid = tid >> 5, lid = tid & 31;
        if (lid == 0) { red[0][wid] = s; red[1][wid] = ss; }
        __syncthreads();
        __shared__ float smu, srstd;
        if (tid == 0) {
            float ts = 0.f, tss = 0.f;
            #pragma unroll
            for (int i = 0; i < 8; ++i) { ts += red[0][i]; tss += red[1][i]; }
            float mu  = ts * (1.0f / Dn);
            float var = tss * (1.0f / Dn) - mu * mu;
            smu = mu; srstd = rsqrtf(var + EPSV);
        }
        __syncthreads();
        const float mu = smu, rstd = srstd;
        float4 g = ((const float4*)gamma1)[tid];
        float4 b = ((const float4*)beta1)[tid];
        uint2 u;
        u.x = pack2(g.x * (v.x - mu) * rstd + b.x, g.y * (v.y - mu) * rstd + b.y);
        u.y = pack2(g.z * (v.z - mu) * rstd + b.z, g.w * (v.w - mu) * rstd + b.w);
        ((uint2*)(xn1 + (size_t)row * Dn))[tid] = u;
    }
}

// ==================== LayerNorm fp16 in -> fp16 out (LN2) ====================
__global__ __launch_bounds__(256) void ln_kernel_h(const __half* __restrict__ x,
                                                   const float* __restrict__ gamma,
                                                   const float* __restrict__ beta,
                                                   __half* __restrict__ out) {
    const int row = blockIdx.x;
    const int tid = threadIdx.x;
    uint2 xr = ((const uint2*)(x + (size_t)row * Dn))[tid];
    float2 a0 = __half22float2(*(__half2*)&xr.x);
    float2 a1 = __half22float2(*(__half2*)&xr.y);
    float s  = a0.x + a0.y + a1.x + a1.y;
    float ss = a0.x*a0.x + a0.y*a0.y + a1.x*a1.x + a1.y*a1.y;
    #pragma unroll
    for (int off = 16; off > 0; off >>= 1) {
        s  += __shfl_xor_sync(0xffffffffu, s,  off);
        ss += __shfl_xor_sync(0xffffffffu, ss, off);
    }
    __shared__ float red[2][8];
    const int wid = tid >> 5, lid = tid & 31;
    if (lid == 0) { red[0][wid] = s; red[1][wid] = ss; }
    __syncthreads();
    __shared__ float smu, srstd;
    if (tid == 0) {
        float ts = 0.f, tss = 0.f;
        #pragma unroll
        for (int i = 0; i < 8; ++i) { ts += red[0][i]; tss += red[1][i]; }
        float mu  = ts * (1.0f / Dn);
        float var = tss * (1.0f / Dn) - mu * mu;
        smu = mu; srstd = rsqrtf(var + EPSV);
    }
    __syncthreads();
    const float mu = smu, rstd = srstd;
    float4 g = ((const float4*)gamma)[tid];
    float4 b = ((const float4*)beta)[tid];
    uint2 u;
    u.x = pack2(g.x * (a0.x - mu) * rstd + b.x, g.y * (a0.y - mu) * rstd + b.y);
    u.y = pack2(g.z * (a1.x - mu) * rstd + b.z, g.w * (a1.y - mu) * rstd + b.w);
    ((uint2*)(out + (size_t)row * Dn))[tid] = u;
}

// ==================== FP16 tensor GEMM, cp.async 4-stage + ldmatrix ====================
#define BM 128
#define BN 128
#define BKH 32
#define STAGES 4
#define TSH 56
#define TILE_BYTES (128*TSH*2)
#define GT_SMEM (STAGES*2*TILE_BYTES)   // 114688 (2 blocks/SM: 229376 < 233472)

// MODE: 1 = fp16 out (scaled), 2 = GLU epilogue,
//       3 = fp16 out + fp32 resid (x1), 4 = fp32 out + fp16 resid (final)
template<int MODE>
__device__ __forceinline__ void gemm_body(
    const __half* __restrict__ A, const __half* __restrict__ Bt,
    const void* __restrict__ Rv, void* __restrict__ Cv,
    int M_, int N_, int K_, float oscale)
{
    extern __shared__ char smem[];
    const uint32_t sbase = smem_u32(smem);

    const int tid = threadIdx.x;
    const int bx = blockIdx.x, by = blockIdx.y;
    const int wid = tid >> 5, lane = tid & 31;
    const int wm = (wid >> 2) * 64, wn = (wid & 3) * 32;

    const int ld_row = tid >> 2;
    const int ld_ch  = tid & 3;

    const int lrow = lane & 15;
    const int lkh  = (lane >> 4) * 8;

    const int nt = K_ >> 5;
    int kload;

    auto issue = [&](int kt, int st) {
        const uint32_t da = sbase + st*(2*TILE_BYTES);
        const uint32_t db = da + TILE_BYTES;
        cp16(da + (ld_row     )*(TSH*2) + ld_ch*16,
             &A[(size_t)(by*BM + ld_row     )*K_ + kt*BKH + ld_ch*8]);
        cp16(da + (ld_row + 64)*(TSH*2) + ld_ch*16,
             &A[(size_t)(by*BM + ld_row + 64)*K_ + kt*BKH + ld_ch*8]);
        cp16(db + (ld_row     )*(TSH*2) + ld_ch*16,
             &Bt[(size_t)(bx*BN + ld_row     )*K_ + kt*BKH + ld_ch*8]);
        cp16(db + (ld_row + 64)*(TSH*2) + ld_ch*16,
             &Bt[(size_t)(bx*BN + ld_row + 64)*K_ + kt*BKH + ld_ch*8]);
    };

    float acc[4][4][4];
    #pragma unroll
    for (int i = 0; i < 4; ++i)
        #pragma unroll
        for (int j = 0; j < 4; ++j)
            #pragma unroll
            for (int e = 0; e < 4; ++e) acc[i][j][e] = 0.f;

    #pragma unroll
    for (int s = 0; s < STAGES-1; ++s) { issue(s, s); cp_commit(); }
    kload = STAGES-1;

    for (int kt = 0; kt < nt; ++kt) {
        cp_wait<STAGES-2>();
        __syncthreads();
        const int st = kt & (STAGES-1);
        const uint32_t sa = sbase + st*(2*TILE_BYTES);
        const uint32_t sb = sa + TILE_BYTES;
        #pragma unroll
        for (int kk = 0; kk < 2; ++kk) {
            uint32_t afr[4][4], bq[2][4];
            #pragma unroll
            for (int i = 0; i < 4; ++i)
                ldsm4(afr[i], sa + ((wm + i*16 + lrow)*TSH + kk*16 + lkh)*2);
            #pragma unroll
            for (int jj = 0; jj < 2; ++jj)
                ldsm4(bq[jj], sb + ((wn + jj*16 + lrow)*TSH + kk*16 + lkh)*2);
            #pragma unroll
            for (int i = 0; i < 4; ++i) {
                #pragma unroll
                for (int jj = 0; jj < 2; ++jj) {
                    mma_f16(acc[i][jj*2  ], afr[i], bq[jj][0], bq[jj][2]);
                    mma_f16(acc[i][jj*2+1], afr[i], bq[jj][1], bq[jj][3]);
                }
            }
        }
        if (kload < nt) { issue(kload, kload & (STAGES-1)); ++kload; }
        cp_commit();
    }

    // epilogue
    const int eg = lane >> 2, et = lane & 3;
    #pragma unroll
    for (int i = 0; i < 4; ++i) {
        const int row0 = by*BM + wm + i*16 + eg;
        const int row1 = row0 + 8;
        #pragma unroll
        for (int j = 0; j < 4; ++j) {
            const int col = bx*BN + wn + j*8 + et*2;
            if (MODE == 2) {
                __half* C = (__half*)Cv;
                const int colh = col >> 1;
                const int No = N_ >> 1;
                float g0 = acc[i][j][0] / (1.f + __expf(-acc[i][j][1]));
                float g1 = acc[i][j][2] / (1.f + __expf(-acc[i][j][3]));
                C[(size_t)row0*No + colh] = __float2half_rn(g0);
                C[(size_t)row1*No + colh] = __float2half_rn(g1);
            } else if (MODE == 1) {
                __half* C = (__half*)Cv;
                *(uint32_t*)&C[(size_t)row0*N_ + col] =
                    pack2(acc[i][j][0]*oscale, acc[i][j][1]*oscale);
                *(uint32_t*)&C[(size_t)row1*N_ + col] =
                    pack2(acc[i][j][2]*oscale, acc[i][j][3]*oscale);
            } else if (MODE == 3) {
                const float* R = (const float*)Rv;
                __half* C = (__half*)Cv;
                float2 r0 = *(const float2*)&R[(size_t)row0*N_ + col];
                float2 r1 = *(const float2*)&R[(size_t)row1*N_ + col];
                *(uint32_t*)&C[(size_t)row0*N_ + col] =
                    pack2(acc[i][j][0] + r0.x, acc[i][j][1] + r0.y);
                *(uint32_t*)&C[(size_t)row1*N_ + col] =
                    pack2(acc[i][j][2] + r1.x, acc[i][j][3] + r1.y);
            } else { // MODE 4
                const __half* R = (const __half*)Rv;
                float* C = (float*)Cv;
                uint32_t r0u = *(const uint32_t*)&R[(size_t)row0*N_ + col];
                uint32_t r1u = *(const uint32_t*)&R[(size_t)row1*N_ + col];
                float2 r0 = __half22float2(*(__half2*)&r0u);
                float2 r1 = __half22float2(*(__half2*)&r1u);
                float2 v0 = { acc[i][j][0] + r0.x, acc[i][j][1] + r0.y };
                float2 v1 = { acc[i][j][2] + r1.x, acc[i][j][3] + r1.y };
                *(float2*)&C[(size_t)row0*N_ + col] = v0;
                *(float2*)&C[(size_t)row1*N_ + col] = v1;
            }
        }
    }
}

template<int MODE>
__global__ __launch_bounds__(256, 2) void gemm_k(
    const __half* __restrict__ A, const __half* __restrict__ Bt,
    const void* __restrict__ Rv, void* __restrict__ Cv,
    int M_, int N_, int K_)
{
    gemm_body<MODE>(A, Bt, Rv, Cv, M_, N_, K_, 1.0f);
}

// fused QKV; q output pre-scaled by (1/sqrt(DH)) * log2(e) for exp2-based softmax
#define QSCALE (0.125f * 1.4426950408889634f)
__global__ __launch_bounds__(256, 2) void gemm_qkv(
    const __half* __restrict__ A, const __half* __restrict__ W,
    __half* __restrict__ q, __half* __restrict__ k, __half* __restrict__ v)
{
    const int z = blockIdx.z;
    const __half* Bt = W + (z == 0 ? WOFF_Q : z == 1 ? WOFF_K : WOFF_V);
    __half* C = (z == 0) ? q : (z == 1) ? k : v;
    gemm_body<1>(A, Bt, nullptr, C, Mn, Dn, Dn, z == 0 ? QSCALE : 1.0f);
}

// ==================== causal flash attention: R12 config (2-stage, qt-pairing, exp2) ====================
#define KVS 72
#define KV_STAGE_BYTES (2*64*KVS*2)
#define ATTN_SMEM (2*KV_STAGE_BYTES)      // 36864
#define NQT (Sn/64)                       // 32

__global__ __launch_bounds__(128, 3) void attn_f16(
    const __half* __restrict__ Q, const __half* __restrict__ K,
    const __half* __restrict__ V, const int* __restrict__ mask,
    __half* __restrict__ O) {
    extern __shared__ __half smh[];
    const uint32_t sm0 = smem_u32(smh);
    __shared__ uint32_t mbits[2][2];

    const int pair = blockIdx.x;          // 0..15
    const int h = blockIdx.y, b = blockIdx.z;
    const int tid = threadIdx.x;
    const int wid = tid >> 5, lane = tid & 31;
    const int g = lane >> 2, t = lane & 3;
    const int lrow = lane & 15;
    const int lkh  = (lane >> 4) * 8;

    #pragma unroll
    for (int ph = 0; ph < 2; ++ph) {
        const int qt = (ph == 0) ? (NQT - 1 - pair) : pair;   // heavy first

        const __half* Qb = Q + ((size_t)(b*Sn + qt*64 + wid*16))*Dn + h*DHn;
        uint32_t qa[4][4];
        #pragma unroll
        for (int ks = 0; ks < 4; ++ks) {
            qa[ks][0] = *(const uint32_t*)&Qb[(size_t)(g    )*Dn + ks*16 + 2*t];
            qa[ks][1] = *(const uint32_t*)&Qb[(size_t)(g + 8)*Dn + ks*16 + 2*t];
            qa[ks][2] = *(const uint32_t*)&Qb[(size_t)(g    )*Dn + ks*16 + 8 + 2*t];
            qa[ks][3] = *(const uint32_t*)&Qb[(size_t)(g + 8)*Dn + ks*16 + 8 + 2*t];
        }

        auto load_kv = [&](int kt, int st) {
            const uint32_t ks_u = sm0 + st*KV_STAGE_BYTES;
            const uint32_t vs_u = ks_u + 64*KVS*2;
            const __half* Kb = K + (size_t)(b*Sn + kt*64)*Dn + h*DHn;
            const __half* Vb = V + (size_t)(b*Sn + kt*64)*Dn + h*DHn;
            #pragma unroll
            for (int c = 0; c < 4; ++c) {
                const int idx = tid + c*128;
                const int rr = idx >> 3, ch = idx & 7;
                cp16(ks_u + rr*(KVS*2) + ch*16, Kb + (size_t)rr*Dn + ch*8);
                cp16(vs_u + rr*(KVS*2) + ch*16, Vb + (size_t)rr*Dn + ch*8);
            }
            if (tid < 64) {
                const int val = mask[b*Sn + kt*64 + tid];
                const unsigned bal = __ballot_sync(0xffffffffu, val != 0);
                if ((tid & 31) == 0) mbits[st][tid >> 5] = bal;
            }
        };

        float o[8][4];
        #pragma unroll
        for (int j = 0; j < 8; ++j)
            #pragma unroll
            for (int e = 0; e < 4; ++e) o[j][e] = 0.f;
        float m0 = -1e30f, m1 = -1e30f, l0 = 0.f, l1 = 0.f;

        const int rowg0 = qt*64 + wid*16 + g;
        const int rowg1 = rowg0 + 8;

        load_kv(0, 0); cp_commit();
        if (qt >= 1) load_kv(1, 1);
        cp_commit();

        int buf = 0;
        for (int kt = 0; kt <= qt; ++kt) {
            cp_wait<1>();
            __syncthreads();
            const uint32_t ks_u = sm0 + buf*KV_STAGE_BYTES;
            const uint32_t vs_u = ks_u + 64*KVS*2;

            float sc[8][4];
            #pragma unroll
            for (int j = 0; j < 8; ++j)
                #pragma unroll
                for (int e = 0; e < 4; ++e) sc[j][e] = 0.f;
            #pragma unroll
            for (int ks = 0; ks < 4; ++ks) {
                #pragma unroll
                for (int jj = 0; jj < 4; ++jj) {
                    uint32_t bq[4];
                    ldsm4(bq, ks_u + ((jj*16 + lrow)*KVS + ks*16 + lkh)*2);
                    mma_f16(sc[jj*2  ], qa[ks], bq[0], bq[2]);
                    mma_f16(sc[jj*2+1], qa[ks], bq[1], bq[3]);
                }
            }

            const uint32_t mb0 = mbits[buf][0], mb1 = mbits[buf][1];
            const bool need_mask = (kt == qt) || ((mb0 & mb1) != 0xffffffffu);
            if (need_mask) {
                #pragma unroll
                for (int j = 0; j < 8; ++j) {
                    #pragma unroll
                    for (int e = 0; e < 4; ++e) {
                        const int cl  = j*8 + t*2 + (e & 1);
                        const int kg  = kt*64 + cl;
                        const int row = (e < 2) ? rowg0 : rowg1;
                        const bool km = (cl < 32) ? ((mb0 >> cl) & 1u)
                                                  : ((mb1 >> (cl - 32)) & 1u);
                        const bool ok = (kg <= row) && km;
                        sc[j][e] = ok ? sc[j][e] : -1e30f;
                    }
                }
            }

            float rm0 = -1e30f, rm1 = -1e30f;
            #pragma unroll
            for (int j = 0; j < 8; ++j) {
                rm0 = fmaxf(rm0, fmaxf(sc[j][0], sc[j][1]));
                rm1 = fmaxf(rm1, fmaxf(sc[j][2], sc[j][3]));
            }
            rm0 = fmaxf(rm0, __shfl_xor_sync(0xffffffffu, rm0, 1));
            rm0 = fmaxf(rm0, __shfl_xor_sync(0xffffffffu, rm0, 2));
            rm1 = fmaxf(rm1, __shfl_xor_sync(0xffffffffu, rm1, 1));
            rm1 = fmaxf(rm1, __shfl_xor_sync(0xffffffffu, rm1, 2));
            const float mn0 = fmaxf(m0, rm0), mn1 = fmaxf(m1, rm1);
            const float al0 = exp2f(m0 - mn0), al1 = exp2f(m1 - mn1);
            float s0 = 0.f, s1 = 0.f;
            #pragma unroll
            for (int j = 0; j < 8; ++j) {
                sc[j][0] = exp2f(sc[j][0] - mn0);
                sc[j][1] = exp2f(sc[j][1] - mn0);
                sc[j][2] = exp2f(sc[j][2] - mn1);
                sc[j][3] = exp2f(sc[j][3] - mn1);
                s0 += sc[j][0] + sc[j][1];
                s1 += sc[j][2] + sc[j][3];
            }
            s0 += __shfl_xor_sync(0xffffffffu, s0, 1);
            s0 += __shfl_xor_sync(0xffffffffu, s0, 2);
            s1 += __shfl_xor_sync(0xffffffffu, s1, 1);
            s1 += __shfl_xor_sync(0xffffffffu, s1, 2);
            l0 = l0 * al0 + s0;  m0 = mn0;
            l1 = l1 * al1 + s1;  m1 = mn1;
            #pragma unroll
            for (int j = 0; j < 8; ++j) {
                o[j][0] *= al0; o[j][1] *= al0;
                o[j][2] *= al1; o[j][3] *= al1;
            }

            #pragma unroll
            for (int ks = 0; ks < 4; ++ks) {
                uint32_t pa[4];
                pa[0] = pack2(sc[2*ks  ][0], sc[2*ks  ][1]);
                pa[1] = pack2(sc[2*ks  ][2], sc[2*ks  ][3]);
                pa[2] = pack2(sc[2*ks+1][0], sc[2*ks+1][1]);
                pa[3] = pack2(sc[2*ks+1][2], sc[2*ks+1][3]);
                #pragma unroll
                for (int jj = 0; jj < 4; ++jj) {
                    uint32_t bq[4];
                    ldsm4t(bq, vs_u + ((ks*16 + lrow)*KVS + jj*16 + lkh)*2);
                    mma_f16(o[jj*2  ], pa, bq[0], bq[1]);
                    mma_f16(o[jj*2+1], pa, bq[2], bq[3]);
                }
            }

            __syncthreads();
            if (kt + 2 <= qt) load_kv(kt + 2, buf);
            cp_commit();
            buf ^= 1;
        }

        const float i0 = 1.f / l0, i1 = 1.f / l1;
        __half* Ob = O + ((size_t)(b*Sn + qt*64 + wid*16))*Dn + h*DHn;
        #pragma unroll
        for (int j = 0; j < 8; ++j) {
            *(uint32_t*)&Ob[(size_t)(g    )*Dn + j*8 + t*2] = pack2(o[j][0]*i0, o[j][1]*i0);
            *(uint32_t*)&Ob[(size_t)(g + 8)*Dn + j*8 + t*2] = pack2(o[j][2]*i1, o[j][3]*i1);
        }
        __syncthreads();
    }
}

// ==================== launch ====================
extern "C" void kernel_launch(void* const* d_in, const int* in_sizes, int n_in,
                              void* d_out, int out_size) {
    const float* x     = (const float*)d_in[0];
    const int*   amask = (const int*)  d_in[1];
    const float* Wq    = (const float*)d_in[2];
    const float* Wk    = (const float*)d_in[3];
    const float* Wv    = (const float*)d_in[4];
    const float* Wo    = (const float*)d_in[5];
    const float* W1    = (const float*)d_in[6];
    const float* W2    = (const float*)d_in[7];
    const float* gamma1= (const float*)d_in[8];
    const float* beta1 = (const float*)d_in[9];
    const float* gamma2= (const float*)d_in[10];
    const float* beta2 = (const float*)d_in[11];
    float* out = (float*)d_out;

    __half *xn1, *q, *k, *v, *attn, *x1, *xn2, *glu, *wh;
    cudaGetSymbolAddress((void**)&xn1,  g_xn1);
    cudaGetSymbolAddress((void**)&q,    g_q);
    cudaGetSymbolAddress((void**)&k,    g_k);
    cudaGetSymbolAddress((void**)&v,    g_v);
    cudaGetSymbolAddress((void**)&attn, g_attn);
    cudaGetSymbolAddress((void**)&x1,   g_x1);
    cudaGetSymbolAddress((void**)&xn2,  g_xn2);
    cudaGetSymbolAddress((void**)&glu,  g_glu);
    cudaGetSymbolAddress((void**)&wh,   g_wh);

    cudaFuncSetAttribute(attn_f16, cudaFuncAttributeMaxDynamicSharedMemorySize, ATTN_SMEM);
    cudaFuncSetAttribute(gemm_qkv, cudaFuncAttributeMaxDynamicSharedMemorySize, GT_SMEM);
    cudaFuncSetAttribute((const void*)gemm_k<2>, cudaFuncAttributeMaxDynamicSharedMemorySize, GT_SMEM);
    cudaFuncSetAttribute((const void*)gemm_k<3>, cudaFuncAttributeMaxDynamicSharedMemorySize, GT_SMEM);
    cudaFuncSetAttribute((const void*)gemm_k<4>, cudaFuncAttributeMaxDynamicSharedMemorySize, GT_SMEM);

    // 0. fused weight convert+transpose + LN1 (single launch)
    prep_all<<<10240 + Mn, 256>>>(Wq, Wk, Wv, Wo, W1, W2, wh, x, gamma1, beta1, xn1);

    // 1. fused Q,K,V projections -> fp16 (q pre-scaled for exp2 softmax)
    dim3 gQKV(Dn/BN, Mn/BM, 3);
    gemm_qkv<<<gQKV, 256, GT_SMEM>>>(xn1, wh, q, k, v);

    // 2. causal attention -> fp16 (balanced qt pairs)
    dim3 gA(NQT/2, Hn, Bn);
    attn_f16<<<gA, 128, ATTN_SMEM>>>(q, k, v, amask, attn);

    // 3. x1 = x + attn@Wo -> fp16
    dim3 gD(Dn/BN, Mn/BM);
    gemm_k<3><<<gD, 256, GT_SMEM>>>(attn, wh + WOFF_O, x, x1, Mn, Dn, Dn);

    // 4. LN2 (fp16 in) -> fp16
    ln_kernel_h<<<Mn, 256>>>(x1, gamma2, beta2, xn2);

    // 5. W1 + GLU fused -> fp16 glu [Mn, 2048]
    dim3 gF(DFF/BN, Mn/BM);
    gemm_k<2><<<gF, 256, GT_SMEM>>>(xn2, wh + WOFF_1, nullptr, glu, Mn, DFF, Dn);

    // 6. out = x1(fp16) + glu@W2 -> fp32
    gemm_k<4><<<gD, 256, GT_SMEM>>>(glu, wh + WOFF_2, x1, out, Mn, Dn, DG);
}